// round 14
// baseline (speedup 1.0000x reference)
#include <cuda_runtime.h>

#define B_    4
#define CDIM  96
#define L_    9216
#define DM    192
#define NS    16
#define RT    6
#define BL    (B_*L_)
#define TT    128         /* dtbc / out tile */
#define NTILE (BL/TT)     /* 288 */
#define G_    96
#define NCH   (L_/G_)     /* 96 */
#define TTP   132         /* fp32 GEMM xs stride */

/* tf32 kernels */
#define GT_TT  64         /* gate/gemm3 token tile */
#define GT_XS  72         /* raw x stride for 64-token tiles (gemm3) */

/* ---- scratch ---- */
__device__ float g_xin[(size_t)B_*DM*L_];
__device__ float g_xc [(size_t)B_*DM*L_];
__device__ float g_kp [(size_t)B_*DM*L_];
__device__ float g_qp [(size_t)B_*DM*L_];
__device__ float g_dl [(size_t)B_*DM*L_];
__device__ float g_z  [(size_t)B_*DM*L_];
__device__ float g_Bs [(size_t)B_*NS*L_];
__device__ float g_Cs [(size_t)B_*NS*L_];
__device__ float g_y  [(size_t)B_*DM*L_];
__device__ float g_P  [(size_t)B_*NCH*DM*NS];
__device__ float g_Hl [(size_t)B_*NCH*DM*NS];
__device__ float g_Hi [(size_t)B_*NCH*DM*NS];

__device__ __forceinline__ float siluf(float v) { return v / (1.0f + __expf(-v)); }

__device__ __forceinline__ unsigned tf32b(float v) {
    unsigned r; asm("cvt.rna.tf32.f32 %0, %1;" : "=r"(r) : "f"(v)); return r;
}

__device__ __forceinline__ void mma8(float* d, const unsigned* a, const unsigned* b) {
    asm volatile("mma.sync.aligned.m16n8k8.row.col.f32.tf32.tf32.f32 "
        "{%0,%1,%2,%3}, {%4,%5,%6,%7}, {%8,%9}, {%0,%1,%2,%3};"
        : "+f"(d[0]), "+f"(d[1]), "+f"(d[2]), "+f"(d[3])
        : "r"(a[0]), "r"(a[1]), "r"(a[2]), "r"(a[3]), "r"(b[0]), "r"(b[1]));
}

/* fragment-layout indices (48-k chunks, 6 ks-steps) */
#define WFI(ct, ks, ln, q) ((((ct)*6 + (ks))*32 + (ln))*4 + (q))
#define XFI(tt, ks, ln, p) ((((tt)*6 + (ks))*32 + (ln))*2 + (p))

/* stage weight chunk (NC rows x 48 k) into frag-layout hi/lo planes */
#define STAGE_W_FRAG(Wh, Wl, NC, LOADEXPR)                                \
    for (int i = tid; i < (NC)*48; i += 512) {                            \
        int c_ = i / 48, k_ = i % 48;                                     \
        float v_ = (LOADEXPR);                                            \
        unsigned h_ = tf32b(v_);                                          \
        int idx_ = WFI(c_ >> 4, k_ >> 3,                                  \
                       ((c_ & 7) << 2) | (k_ & 3),                        \
                       ((c_ >> 3) & 1) | ((k_ >> 2) & 1) << 1);           \
        (Wh)[idx_] = __uint_as_float(h_);                                 \
        (Wl)[idx_] = v_ - __uint_as_float(h_);                            \
    }

/* stage x chunk (48 k x TTn tokens) into frag-layout hi/lo planes */
#define STAGE_X_FRAG(Xh, Xl, TTn, LOADEXPR)                               \
    for (int i = tid; i < 48*(TTn); i += 512) {                           \
        int k_ = i / (TTn), t_ = i % (TTn);                               \
        float v_ = (LOADEXPR);                                            \
        unsigned h_ = tf32b(v_);                                          \
        int idx_ = XFI(t_ >> 3, k_ >> 3,                                  \
                       ((t_ & 7) << 2) | (k_ & 3), (k_ >> 2) & 1);        \
        (Xh)[idx_] = __uint_as_float(h_);                                 \
        (Xl)[idx_] = v_ - __uint_as_float(h_);                            \
    }

/* A frag: 2x LDS.128 from frag-layout planes */
#define AFRAG_F(AH, AL_, Wh, Wl, ct, ks) {                                \
    float4 h4_ = *(const float4*)&(Wh)[WFI(ct, ks, lane, 0)];             \
    float4 l4_ = *(const float4*)&(Wl)[WFI(ct, ks, lane, 0)];             \
    AH[0]=__float_as_uint(h4_.x); AH[1]=__float_as_uint(h4_.y);           \
    AH[2]=__float_as_uint(h4_.z); AH[3]=__float_as_uint(h4_.w);           \
    AL_[0]=__float_as_uint(l4_.x); AL_[1]=__float_as_uint(l4_.y);         \
    AL_[2]=__float_as_uint(l4_.z); AL_[3]=__float_as_uint(l4_.w); }

/* B frag: 2x LDS.64 from frag-layout planes */
#define BFRAG_F(BH, BL_, Xh, Xl, tt, ks) {                                \
    float2 h2_ = *(const float2*)&(Xh)[XFI(tt, ks, lane, 0)];             \
    float2 l2_ = *(const float2*)&(Xl)[XFI(tt, ks, lane, 0)];             \
    BH[0]=__float_as_uint(h2_.x); BH[1]=__float_as_uint(h2_.y);           \
    BL_[0]=__float_as_uint(l2_.x); BL_[1]=__float_as_uint(l2_.y); }

/* B frag from raw strided smem (register split) — gemm3 only */
#define BFRAG_R(BH, BL_, Xs, STR, kb, t) {                                \
    float v0_ = (Xs)[((kb)+(lane&3))*(STR) + (t)];                        \
    float v1_ = (Xs)[((kb)+(lane&3)+4)*(STR) + (t)];                      \
    BH[0] = tf32b(v0_); BL_[0] = tf32b(v0_ - __uint_as_float(BH[0]));     \
    BH[1] = tf32b(v1_); BL_[1] = tf32b(v1_ - __uint_as_float(BH[1])); }

/* ==== fused 3x GEMM (in_proj / K / Q), LN fused, A frag-layout ====
   TT=64 tokens, K=96 in 2 chunks of 48. 16 warps = 4 ch(48) x 4 tok(16). */
__global__ void __launch_bounds__(512, 2)
gemm3_tf32(const float* __restrict__ x, const float* __restrict__ Kin,
           const float* __restrict__ Qin, const float* __restrict__ in_w,
           const float* __restrict__ k_w, const float* __restrict__ k_b,
           const float* __restrict__ k_ln_g, const float* __restrict__ k_ln_b,
           const float* __restrict__ q_w, const float* __restrict__ q_b,
           const float* __restrict__ q_ln_g, const float* __restrict__ q_ln_b)
{
    extern __shared__ float sm[];
    float* xs = sm;                      // 96*GT_XS (raw)
    float* wh = sm + 96*GT_XS;           // 192*48 frag
    float* wl = wh + 192*48;             // 192*48 frag
    float* mean_s = wl + 192*48;         // 64
    float* rstd_s = mean_s + 64;         // 64

    int sel = blockIdx.y;
    const float* src  = (sel==0) ? x    : (sel==1 ? Kin : Qin);
    const float* W    = (sel==0) ? in_w : (sel==1 ? k_w : q_w);
    const float* bias = (sel==0) ? 0    : (sel==1 ? k_b : q_b);
    const float* lng  = (sel==1) ? k_ln_g : q_ln_g;
    const float* lnb  = (sel==1) ? k_ln_b : q_ln_b;

    int tid = threadIdx.x, lane = tid & 31, wid = tid >> 5;
    int tok0 = blockIdx.x * GT_TT;
    int b = tok0 / L_, l0 = tok0 % L_;
    const float* srcb = src + ((size_t)b*CDIM)*L_ + l0;

    for (int i = tid; i < CDIM*GT_TT; i += 512) {
        int t = i % GT_TT, k = i / GT_TT;
        xs[k*GT_XS + t] = srcb[(size_t)k*L_ + t];
    }
    __syncthreads();

    if (sel != 0) {
        if (tid < GT_TT) {
            float s = 0.f, ss = 0.f;
            for (int c = 0; c < CDIM; c++) { float v = xs[c*GT_XS + tid]; s += v; ss += v*v; }
            float m = s * (1.0f/CDIM);
            float var = ss * (1.0f/CDIM) - m*m;
            mean_s[tid] = m; rstd_s[tid] = rsqrtf(var + 1e-5f);
        }
        __syncthreads();
        for (int i = tid; i < CDIM*GT_TT; i += 512) {
            int t = i % GT_TT, c = i / GT_TT;
            xs[c*GT_XS + t] = (xs[c*GT_XS + t] - mean_s[t]) * rstd_s[t] * lng[c] + lnb[c];
        }
    }

    int wc = (wid & 3) * 48;
    int wt = (wid >> 2) * 16;
    int ct0 = (wid & 3) * 3;

    float acc[3][2][4];
    #pragma unroll
    for (int m = 0; m < 3; m++)
        #pragma unroll
        for (int n = 0; n < 2; n++)
            #pragma unroll
            for (int q = 0; q < 4; q++) acc[m][n][q] = 0.f;

    for (int kc = 0; kc < 2; kc++) {
        __syncthreads();
        STAGE_W_FRAG(wh, wl, DM, W[(size_t)c_*CDIM + kc*48 + k_])
        __syncthreads();

        #pragma unroll
        for (int ks = 0; ks < 6; ks++) {
            int xk = kc*48 + ks*8;
            unsigned bh[2][2], bl[2][2];
            #pragma unroll
            for (int n = 0; n < 2; n++) {
                int t = wt + n*8 + (lane>>2);
                BFRAG_R(bh[n], bl[n], xs, GT_XS, xk, t)
            }
            #pragma unroll
            for (int m = 0; m < 3; m++) {
                unsigned ah[4], al[4];
                AFRAG_F(ah, al, wh, wl, ct0 + m, ks)
                #pragma unroll
                for (int n = 0; n < 2; n++) {
                    mma8(acc[m][n], ah, bl[n]);
                    mma8(acc[m][n], al, bh[n]);
                    mma8(acc[m][n], ah, bh[n]);
                }
            }
        }
    }

    float* dst = (sel == 0) ? g_xin : ((sel == 1) ? g_kp : g_qp);
    float* dstb = dst + ((size_t)b*DM)*L_ + l0;
    #pragma unroll
    for (int m = 0; m < 3; m++) {
        int c = wc + m*16 + (lane>>2);
        float bv0 = bias ? bias[c] : 0.f;
        float bv1 = bias ? bias[c+8] : 0.f;
        #pragma unroll
        for (int n = 0; n < 2; n++) {
            int t = wt + n*8 + 2*(lane&3);
            float2 v0, v1;
            v0.x = acc[m][n][0] + bv0; v0.y = acc[m][n][1] + bv0;
            v1.x = acc[m][n][2] + bv1; v1.y = acc[m][n][3] + bv1;
            if (sel != 0) { v0.x = siluf(v0.x); v0.y = siluf(v0.y);
                            v1.x = siluf(v1.x); v1.y = siluf(v1.y); }
            *(float2*)&dstb[(size_t)c*L_ + t] = v0;
            *(float2*)&dstb[(size_t)(c+8)*L_ + t] = v1;
        }
    }
}

/* ============ depthwise causal conv (k=4) + silu ============ */
__global__ void __launch_bounds__(256)
conv_silu(const float* __restrict__ cw, const float* __restrict__ cb)
{
    int gid = blockIdx.x * blockDim.x + threadIdx.x;
    if (gid >= B_*DM*L_) return;
    int l  = gid % L_;
    int bd = gid / L_;
    int d  = bd % DM;
    const float* p = g_xin + (size_t)bd*L_ + l;
    float acc = cb[d] + cw[d*4+3] * p[0];
    if (l >= 1) acc = fmaf(cw[d*4+2], p[-1], acc);
    if (l >= 2) acc = fmaf(cw[d*4+1], p[-2], acc);
    if (l >= 3) acc = fmaf(cw[d*4+0], p[-3], acc);
    g_xc[gid] = siluf(acc);
}

/* ============ dtbc (fp32, proven R7 version) ============ */
#define FMA_GROUP16(j)                                                   \
    {   float4 wq = *(const float4*)&wrow[kk];                           \
        acc[0][j] = fmaf(wq.x, xq[0].x, acc[0][j]);                      \
        acc[1][j] = fmaf(wq.x, xq[0].y, acc[1][j]);                      \
        acc[2][j] = fmaf(wq.x, xq[0].z, acc[2][j]);                      \
        acc[3][j] = fmaf(wq.x, xq[0].w, acc[3][j]);                      \
        acc[0][j] = fmaf(wq.y, xq[1].x, acc[0][j]);                      \
        acc[1][j] = fmaf(wq.y, xq[1].y, acc[1][j]);                      \
        acc[2][j] = fmaf(wq.y, xq[1].z, acc[2][j]);                      \
        acc[3][j] = fmaf(wq.y, xq[1].w, acc[3][j]);                      \
        acc[0][j] = fmaf(wq.z, xq[2].x, acc[0][j]);                      \
        acc[1][j] = fmaf(wq.z, xq[2].y, acc[1][j]);                      \
        acc[2][j] = fmaf(wq.z, xq[2].z, acc[2][j]);                      \
        acc[3][j] = fmaf(wq.z, xq[2].w, acc[3][j]);                      \
        acc[0][j] = fmaf(wq.w, xq[3].x, acc[0][j]);                      \
        acc[1][j] = fmaf(wq.w, xq[3].y, acc[1][j]);                      \
        acc[2][j] = fmaf(wq.w, xq[3].z, acc[2][j]);                      \
        acc[3][j] = fmaf(wq.w, xq[3].w, acc[3][j]); }

__global__ void __launch_bounds__(512)
dtbc_kernel(const float* __restrict__ dtbc_w, const float* __restrict__ dt_w,
            const float* __restrict__ dt_b)
{
    extern __shared__ float sm[];
    float* xs   = sm;                    // 96*TTP
    float* ws   = xs + 96*TTP;           // 38*96
    float* dbl  = ws + 38*96;            // 38*TTP
    float* dtw  = dbl + 38*TTP;          // 192*6
    float* dtb  = dtw + 192*6;           // 192
    int tid = threadIdx.x;
    int tok0 = blockIdx.x * TT;
    int b = tok0 / L_, l0 = tok0 % L_;

    for (int i = tid; i < DM*RT; i += 512) dtw[i] = dt_w[i];
    for (int i = tid; i < DM;    i += 512) dtb[i] = dt_b[i];

    int tx = tid & 31, ty = tid >> 5;
    float acc[4][3];
    #pragma unroll
    for (int m = 0; m < 4; m++)
        #pragma unroll
        for (int j = 0; j < 3; j++) acc[m][j] = 0.f;

    for (int kc = 0; kc < 4; kc++) {
        const float* src = (kc < 2) ? g_xc : g_kp;
        int k0 = (kc & 1) * 96;
        __syncthreads();
        for (int i = tid; i < 96*TT; i += 512) {
            int t = i % TT, k = i / TT;
            xs[k*TTP + t] = src[((size_t)b*DM + k0 + k)*L_ + l0 + t];
        }
        for (int i = tid; i < 38*96; i += 512) {
            int c = i / 96, kk = i % 96;
            ws[i] = dtbc_w[c*384 + kc*96 + kk];
        }
        __syncthreads();
        #pragma unroll 2
        for (int kk = 0; kk < 96; kk += 4) {
            float4 xq[4];
            #pragma unroll
            for (int q = 0; q < 4; q++)
                xq[q] = *(const float4*)&xs[(kk+q)*TTP + tx*4];
            #pragma unroll
            for (int j = 0; j < 3; j++) {
                int c = ty + 16*j;
                if (c < 38) {
                    const float* wrow = &ws[c*96];
                    FMA_GROUP16(j)
                }
            }
        }
    }
    __syncthreads();
    #pragma unroll
    for (int j = 0; j < 3; j++) {
        int c = ty + 16*j;
        if (c < 38) {
            float4 v; v.x = acc[0][j]; v.y = acc[1][j]; v.z = acc[2][j]; v.w = acc[3][j];
            *(float4*)&dbl[c*TTP + tx*4] = v;
        }
    }
    __syncthreads();

    for (int i = tid; i < DM*TT; i += 512) {
        int t = i % TT, d = i / TT;
        float s = 2.0f * dtb[d];
        #pragma unroll
        for (int r = 0; r < RT; r++) s = fmaf(dbl[r*TTP + t], dtw[d*RT + r], s);
        float dl = (s > 20.f) ? s : log1pf(__expf(s));
        g_dl[((size_t)b*DM + d)*L_ + l0 + t] = dl;
    }
    for (int i = tid; i < 2*NS*TT; i += 512) {
        int t = i % TT, q = i / TT;
        float v = dbl[(RT + q)*TTP + t];
        if (q < NS) g_Bs[((size_t)b*NS + q)*L_ + l0 + t] = v;
        else        g_Cs[((size_t)b*NS + (q-NS))*L_ + l0 + t] = v;
    }
}

/* ==== gate: z = silu(cat(xc,qp) @ gate_w^T + b), full frag-layout ====
   TT=64 tokens, K=384 in 8 chunks of 48. */
__global__ void __launch_bounds__(512, 2)
gate_tf32(const float* __restrict__ gate_w, const float* __restrict__ gate_b)
{
    extern __shared__ float sm[];
    float* xh = sm;                  // 48*64 frag
    float* xl = xh + 48*GT_TT;
    float* wh = xl + 48*GT_TT;       // 192*48 frag
    float* wl = wh + 192*48;
    int tid = threadIdx.x, lane = tid & 31, wid = tid >> 5;
    int tok0 = blockIdx.x * GT_TT;
    int b = tok0 / L_, l0 = tok0 % L_;
    int wc = (wid & 3) * 48;
    int wt = (wid >> 2) * 16;
    int ct0 = (wid & 3) * 3;
    int tt0 = (wid >> 2) * 2;

    float acc[3][2][4];
    #pragma unroll
    for (int m = 0; m < 3; m++)
        #pragma unroll
        for (int n = 0; n < 2; n++)
            #pragma unroll
            for (int q = 0; q < 4; q++) acc[m][n][q] = 0.f;

    for (int kc = 0; kc < 8; kc++) {
        const float* src = (kc < 4) ? g_xc : g_qp;
        int ch0 = (kc & 3) * 48;
        __syncthreads();
        STAGE_X_FRAG(xh, xl, GT_TT, src[((size_t)b*DM + ch0 + k_)*L_ + l0 + t_])
        STAGE_W_FRAG(wh, wl, DM, gate_w[(size_t)c_*384 + kc*48 + k_])
        __syncthreads();

        #pragma unroll
        for (int ks = 0; ks < 6; ks++) {
            unsigned bh[2][2], bl[2][2];
            #pragma unroll
            for (int n = 0; n < 2; n++)
                BFRAG_F(bh[n], bl[n], xh, xl, tt0 + n, ks)
            #pragma unroll
            for (int m = 0; m < 3; m++) {
                unsigned ah[4], al[4];
                AFRAG_F(ah, al, wh, wl, ct0 + m, ks)
                #pragma unroll
                for (int n = 0; n < 2; n++) {
                    mma8(acc[m][n], ah, bl[n]);
                    mma8(acc[m][n], al, bh[n]);
                    mma8(acc[m][n], ah, bh[n]);
                }
            }
        }
    }

    float* dstb = g_z + ((size_t)b*DM)*L_ + l0;
    #pragma unroll
    for (int m = 0; m < 3; m++) {
        int c = wc + m*16 + (lane>>2);
        float bv0 = gate_b[c], bv1 = gate_b[c+8];
        #pragma unroll
        for (int n = 0; n < 2; n++) {
            int t = wt + n*8 + 2*(lane&3);
            float2 v0, v1;
            v0.x = siluf(acc[m][n][0] + bv0); v0.y = siluf(acc[m][n][1] + bv0);
            v1.x = siluf(acc[m][n][2] + bv1); v1.y = siluf(acc[m][n][3] + bv1);
            *(float2*)&dstb[(size_t)c*L_ + t] = v0;
            *(float2*)&dstb[(size_t)(c+8)*L_ + t] = v1;
        }
    }
}

/* ============ chunked selective scan (unchanged) ============ */
__global__ void __launch_bounds__(256)
scan1(const float* __restrict__ A_log)
{
    __shared__ float dls[16*97], xcs[16*97], bs[16*97];
    int b = blockIdx.z, ch = blockIdx.y, dblk = blockIdx.x;
    int d0 = dblk*16;
    int tid = threadIdx.x;
    for (int i = tid; i < 16*G_; i += 256) {
        int r = i / G_, t = i % G_;
        dls[r*97+t] = g_dl[((size_t)b*DM + d0 + r)*L_ + ch*G_ + t];
        xcs[r*97+t] = g_xc[((size_t)b*DM + d0 + r)*L_ + ch*G_ + t];
        bs [r*97+t] = g_Bs[((size_t)b*NS + r)*L_ + ch*G_ + t];
    }
    __syncthreads();
    int n = tid & 15, dloc = tid >> 4;
    int d = d0 + dloc;
    float A = -__expf(A_log[d*NS + n]);
    float h = 0.f, S = 0.f;
    #pragma unroll 4
    for (int t = 0; t < G_; t++) {
        float dl = dls[dloc*97+t];
        float a = __expf(dl * A);
        S += dl;
        h = fmaf(a, h, dl * xcs[dloc*97+t] * bs[n*97+t]);
    }
    size_t o = (((size_t)(b*NCH + ch))*DM + d)*NS + n;
    g_P[o] = __expf(A * S); g_Hl[o] = h;
}

__global__ void __launch_bounds__(256)
scan2()
{
    int idx = blockIdx.x * blockDim.x + threadIdx.x;
    if (idx >= B_*DM*NS) return;
    int b = idx / (DM*NS);
    int dn = idx % (DM*NS);
    float h = 0.f;
    for (int ch = 0; ch < NCH; ch++) {
        size_t o = ((size_t)(b*NCH + ch))*(DM*NS) + dn;
        g_Hi[o] = h;
        h = fmaf(g_P[o], h, g_Hl[o]);
    }
}

__global__ void __launch_bounds__(256)
scan3(const float* __restrict__ A_log, const float* __restrict__ Dp)
{
    __shared__ float dls[16*97], xcs[16*97], bs[16*97], cs[16*97], zs[16*97], ys[16*97];
    int b = blockIdx.z, ch = blockIdx.y, dblk = blockIdx.x;
    int d0 = dblk*16;
    int tid = threadIdx.x;
    for (int i = tid; i < 16*G_; i += 256) {
        int r = i / G_, t = i % G_;
        size_t db = ((size_t)b*DM + d0 + r)*L_ + ch*G_ + t;
        size_t nb = ((size_t)b*NS + r)*L_ + ch*G_ + t;
        dls[r*97+t] = g_dl[db];
        xcs[r*97+t] = g_xc[db];
        zs [r*97+t] = g_z [db];
        bs [r*97+t] = g_Bs[nb];
        cs [r*97+t] = g_Cs[nb];
    }
    __syncthreads();
    int n = tid & 15, dloc = tid >> 4;
    int d = d0 + dloc;
    float A = -__expf(A_log[d*NS + n]);
    size_t o = (((size_t)(b*NCH + ch))*DM + d)*NS + n;
    float h = g_Hi[o];
    float Dd = Dp[d];
    for (int t = 0; t < G_; t++) {
        float dl = dls[dloc*97+t];
        float u  = xcs[dloc*97+t];
        float a = __expf(dl * A);
        h = fmaf(a, h, dl * u * bs[n*97+t]);
        float v = h * cs[n*97+t];
        v += __shfl_xor_sync(0xffffffffu, v, 1);
        v += __shfl_xor_sync(0xffffffffu, v, 2);
        v += __shfl_xor_sync(0xffffffffu, v, 4);
        v += __shfl_xor_sync(0xffffffffu, v, 8);
        if (n == 0)
            ys[dloc*97+t] = (v + u * Dd) * zs[dloc*97+t];
    }
    __syncthreads();
    for (int i = tid; i < 16*G_; i += 256) {
        int r = i / G_, t = i % G_;
        g_y[((size_t)b*DM + d0 + r)*L_ + ch*G_ + t] = ys[r*97+t];
    }
}

/* ==== out projection: out = y @ out_w^T, full frag-layout ====
   TT=128 tokens, N=96, K=192 in 4 chunks of 48. 16 warps = 2 ch x 8 tok. */
__global__ void __launch_bounds__(512, 2)
gemm_out_tf32(const float* __restrict__ out_w, float* __restrict__ out)
{
    extern __shared__ float sm[];
    float* xh = sm;                  // 48*128 frag
    float* xl = xh + 48*TT;
    float* wh = xl + 48*TT;          // 96*48 frag
    float* wl = wh + 96*48;
    int tid = threadIdx.x, lane = tid & 31, wid = tid >> 5;
    int tok0 = blockIdx.x * TT;
    int b = tok0 / L_, l0 = tok0 % L_;
    int wc = (wid & 1) * 48;
    int wt = (wid >> 1) * 16;
    int ct0 = (wid & 1) * 3;
    int tt0 = (wid >> 1) * 2;

    float acc[3][2][4];
    #pragma unroll
    for (int m = 0; m < 3; m++)
        #pragma unroll
        for (int n = 0; n < 2; n++)
            #pragma unroll
            for (int q = 0; q < 4; q++) acc[m][n][q] = 0.f;

    for (int kc = 0; kc < 4; kc++) {
        __syncthreads();
        STAGE_X_FRAG(xh, xl, TT, g_y[((size_t)b*DM + kc*48 + k_)*L_ + l0 + t_])
        STAGE_W_FRAG(wh, wl, CDIM, out_w[(size_t)c_*DM + kc*48 + k_])
        __syncthreads();

        #pragma unroll
        for (int ks = 0; ks < 6; ks++) {
            unsigned bh[2][2], bl[2][2];
            #pragma unroll
            for (int n = 0; n < 2; n++)
                BFRAG_F(bh[n], bl[n], xh, xl, tt0 + n, ks)
            #pragma unroll
            for (int m = 0; m < 3; m++) {
                unsigned ah[4], al[4];
                AFRAG_F(ah, al, wh, wl, ct0 + m, ks)
                #pragma unroll
                for (int n = 0; n < 2; n++) {
                    mma8(acc[m][n], ah, bl[n]);
                    mma8(acc[m][n], al, bh[n]);
                    mma8(acc[m][n], ah, bh[n]);
                }
            }
        }
    }

    float* ob = out + ((size_t)b*CDIM)*L_ + l0;
    #pragma unroll
    for (int m = 0; m < 3; m++) {
        int c = wc + m*16 + (lane>>2);
        #pragma unroll
        for (int n = 0; n < 2; n++) {
            int t = wt + n*8 + 2*(lane&3);
            float2 v0, v1;
            v0.x = acc[m][n][0]; v0.y = acc[m][n][1];
            v1.x = acc[m][n][2]; v1.y = acc[m][n][3];
            *(float2*)&ob[(size_t)c*L_ + t] = v0;
            *(float2*)&ob[(size_t)(c+8)*L_ + t] = v1;
        }
    }
}

/* ============ host launcher ============ */
extern "C" void kernel_launch(void* const* d_in, const int* in_sizes, int n_in,
                              void* d_out, int out_size)
{
    const float* x         = (const float*)d_in[0];
    const float* Kin       = (const float*)d_in[1];
    const float* Qin       = (const float*)d_in[2];
    const float* in_proj_w = (const float*)d_in[3];
    const float* conv_w    = (const float*)d_in[4];
    const float* conv_b    = (const float*)d_in[5];
    const float* k_ln_g    = (const float*)d_in[6];
    const float* k_ln_b    = (const float*)d_in[7];
    const float* k_w       = (const float*)d_in[8];
    const float* k_b       = (const float*)d_in[9];
    const float* q_ln_g    = (const float*)d_in[10];
    const float* q_ln_b    = (const float*)d_in[11];
    const float* q_w       = (const float*)d_in[12];
    const float* q_b       = (const float*)d_in[13];
    const float* dtbc_w    = (const float*)d_in[14];
    const float* dt_w      = (const float*)d_in[15];
    const float* dt_b      = (const float*)d_in[16];
    const float* gate_w    = (const float*)d_in[17];
    const float* gate_b    = (const float*)d_in[18];
    const float* A_log     = (const float*)d_in[19];
    const float* Dp        = (const float*)d_in[20];
    const float* out_w     = (const float*)d_in[21];
    float* out = (float*)d_out;

    const int SMEM_G3 = (96*GT_XS + 2*192*48 + 128) * 4;              /* ~101 KB */
    const int SMEM_D  = (96*TTP + 38*96 + 38*TTP + 192*6 + 192) * 4;  /* ~89 KB  */
    const int SMEM_GT = (2*48*GT_TT + 2*192*48) * 4;                  /* ~98 KB  */
    const int SMEM_OT = (2*48*TT + 2*96*48) * 4;                      /* ~86 KB  */

    cudaFuncSetAttribute(gemm3_tf32,    cudaFuncAttributeMaxDynamicSharedMemorySize, SMEM_G3);
    cudaFuncSetAttribute(dtbc_kernel,   cudaFuncAttributeMaxDynamicSharedMemorySize, SMEM_D);
    cudaFuncSetAttribute(gate_tf32,     cudaFuncAttributeMaxDynamicSharedMemorySize, SMEM_GT);
    cudaFuncSetAttribute(gemm_out_tf32, cudaFuncAttributeMaxDynamicSharedMemorySize, SMEM_OT);

    /* 1. fused in_proj + K + Q (tensor cores, LN fused, A frag-layout) */
    gemm3_tf32<<<dim3(BL/GT_TT,3), 512, SMEM_G3>>>(x, Kin, Qin, in_proj_w,
        k_w, k_b, k_ln_g, k_ln_b, q_w, q_b, q_ln_g, q_ln_b);
    /* 2. depthwise conv + silu */
    conv_silu<<<(B_*DM*L_)/256, 256>>>(conv_w, conv_b);
    /* 3. dtbc -> delta, B, C (fp32) */
    dtbc_kernel<<<NTILE, 512, SMEM_D>>>(dtbc_w, dt_w, dt_b);
    /* 4. gate -> silu(z) (tensor cores, full frag-layout) */
    gate_tf32<<<BL/GT_TT, 512, SMEM_GT>>>(gate_w, gate_b);
    /* 5-7. chunked selective scan */
    scan1<<<dim3(DM/16, NCH, B_), 256>>>(A_log);
    scan2<<<(B_*DM*NS)/256, 256>>>();
    scan3<<<dim3(DM/16, NCH, B_), 256>>>(A_log, Dp);
    /* 8. output projection (tensor cores, full frag-layout) */
    gemm_out_tf32<<<NTILE, 512, SMEM_OT>>>(out_w, out);
}

// round 15
// speedup vs baseline: 1.1393x; 1.1393x over previous
#include <cuda_runtime.h>
#include <cuda_bf16.h>

#define B_    4
#define CDIM  96
#define L_    9216
#define DM    192
#define NS    16
#define RT    6
#define BL    (B_*L_)
#define TT    128         /* dtbc / out token tile */
#define NTILE (BL/TT)     /* 288 */
#define G_    96
#define NCH   (L_/G_)     /* 96 */
#define TTP   132         /* fp32 GEMM xs stride */

/* bf16-split kernels */
#define GT_TT  64         /* gate/gemm3 token tile */
#define GT_XS  72         /* raw x float stride (gemm3 LN buffer) */
#define WSTR2  28         /* W plane stride in uint2 (24 words + 4 pad) */
#define XS_G   68         /* X plane stride in uint2, gate/gemm3 (>=64, ==4 mod 16) */
#define XS_O   132        /* X plane stride in uint2, out (>=128, ==4 mod 16) */

/* ---- scratch ---- */
__device__ float g_xin[(size_t)B_*DM*L_];
__device__ float g_xc [(size_t)B_*DM*L_];
__device__ float g_kp [(size_t)B_*DM*L_];
__device__ float g_qp [(size_t)B_*DM*L_];
__device__ float g_dl [(size_t)B_*DM*L_];
__device__ float g_z  [(size_t)B_*DM*L_];
__device__ float g_Bs [(size_t)B_*NS*L_];
__device__ float g_Cs [(size_t)B_*NS*L_];
__device__ float g_y  [(size_t)B_*DM*L_];
__device__ float g_P  [(size_t)B_*NCH*DM*NS];
__device__ float g_Hl [(size_t)B_*NCH*DM*NS];
__device__ float g_Hi [(size_t)B_*NCH*DM*NS];

__device__ __forceinline__ float siluf(float v) { return v / (1.0f + __expf(-v)); }

/* bf16 hi/lo split of a pair of consecutive-k floats -> packed words */
__device__ __forceinline__ uint2 bfsplit2(float v0, float v1) {
    __nv_bfloat16 h0 = __float2bfloat16(v0);
    __nv_bfloat16 h1 = __float2bfloat16(v1);
    __nv_bfloat16 l0 = __float2bfloat16(v0 - __bfloat162float(h0));
    __nv_bfloat16 l1 = __float2bfloat16(v1 - __bfloat162float(h1));
    uint2 r;
    r.x = ((unsigned)__bfloat16_as_ushort(h1) << 16) | __bfloat16_as_ushort(h0);
    r.y = ((unsigned)__bfloat16_as_ushort(l1) << 16) | __bfloat16_as_ushort(l0);
    return r;
}

/* D += A(16x16) * B(16x8), bf16 inputs, f32 accum */
__device__ __forceinline__ void mma16(float* d, const unsigned* a, const unsigned* b) {
    asm volatile("mma.sync.aligned.m16n8k16.row.col.f32.bf16.bf16.f32 "
        "{%0,%1,%2,%3}, {%4,%5,%6,%7}, {%8,%9}, {%0,%1,%2,%3};"
        : "+f"(d[0]), "+f"(d[1]), "+f"(d[2]), "+f"(d[3])
        : "r"(a[0]), "r"(a[1]), "r"(a[2]), "r"(a[3]), "r"(b[0]), "r"(b[1]));
}

/* A frag (hi+lo) via 4x LDS.64: c = channel row of this m-tile's lane */
#define AFRAG2(AH, AL_, Wp, c, ksb) {                                     \
    uint2 q0_ = (Wp)[(c)*WSTR2 + (ksb) + (lane&3)];                       \
    uint2 q1_ = (Wp)[((c)+8)*WSTR2 + (ksb) + (lane&3)];                   \
    uint2 q2_ = (Wp)[(c)*WSTR2 + (ksb) + (lane&3) + 4];                   \
    uint2 q3_ = (Wp)[((c)+8)*WSTR2 + (ksb) + (lane&3) + 4];               \
    AH[0]=q0_.x; AH[1]=q1_.x; AH[2]=q2_.x; AH[3]=q3_.x;                   \
    AL_[0]=q0_.y; AL_[1]=q1_.y; AL_[2]=q2_.y; AL_[3]=q3_.y; }

/* B frag (hi+lo) via 2x LDS.64 */
#define BFRAG2(BH, BL_, Xp, XSTR, ksb, t) {                               \
    uint2 q0_ = (Xp)[((ksb) + (lane&3))*(XSTR) + (t)];                    \
    uint2 q1_ = (Xp)[((ksb) + (lane&3) + 4)*(XSTR) + (t)];                \
    BH[0]=q0_.x; BH[1]=q1_.x; BL_[0]=q0_.y; BL_[1]=q1_.y; }

/* stage 48-k W chunk (NC rows) into uint2 hi/lo plane */
#define STAGE_W2(Wp, NC, ROWSTR, SRC, KOFF)                               \
    for (int i = tid; i < (NC)*24; i += 512) {                            \
        int c_ = i / 24, k2_ = i % 24;                                    \
        float2 v_ = *(const float2*)&(SRC)[(size_t)c_*(ROWSTR) + (KOFF) + 2*k2_]; \
        (Wp)[c_*WSTR2 + k2_] = bfsplit2(v_.x, v_.y);                      \
    }

/* ==== fused 3x GEMM (in_proj / K / Q), LN fused, bf16 3-term split ====
   64 tokens, K=96 in 2 chunks of 48. 16 warps = 4 ch(48) x 4 tok(16). */
__global__ void __launch_bounds__(512, 2)
gemm3_bf(const float* __restrict__ x, const float* __restrict__ Kin,
         const float* __restrict__ Qin, const float* __restrict__ in_w,
         const float* __restrict__ k_w, const float* __restrict__ k_b,
         const float* __restrict__ k_ln_g, const float* __restrict__ k_ln_b,
         const float* __restrict__ q_w, const float* __restrict__ q_b,
         const float* __restrict__ q_ln_g, const float* __restrict__ q_ln_b)
{
    extern __shared__ float sm[];
    float* xs = sm;                              // 96*GT_XS raw
    uint2* wsp = (uint2*)(sm + 96*GT_XS);        // 192*WSTR2
    uint2* xsp = wsp + 192*WSTR2;                // 24*XS_G
    float* mean_s = (float*)(xsp + 24*XS_G);     // 64
    float* rstd_s = mean_s + 64;                 // 64

    int sel = blockIdx.y;
    const float* src  = (sel==0) ? x    : (sel==1 ? Kin : Qin);
    const float* W    = (sel==0) ? in_w : (sel==1 ? k_w : q_w);
    const float* bias = (sel==0) ? 0    : (sel==1 ? k_b : q_b);
    const float* lng  = (sel==1) ? k_ln_g : q_ln_g;
    const float* lnb  = (sel==1) ? k_ln_b : q_ln_b;

    int tid = threadIdx.x, lane = tid & 31, wid = tid >> 5;
    int tok0 = blockIdx.x * GT_TT;
    int b = tok0 / L_, l0 = tok0 % L_;
    const float* srcb = src + ((size_t)b*CDIM)*L_ + l0;

    for (int i = tid; i < CDIM*GT_TT; i += 512) {
        int t = i % GT_TT, k = i / GT_TT;
        xs[k*GT_XS + t] = srcb[(size_t)k*L_ + t];
    }
    __syncthreads();

    if (sel != 0) {
        if (tid < GT_TT) {
            float s = 0.f, ss = 0.f;
            for (int c = 0; c < CDIM; c++) { float v = xs[c*GT_XS + tid]; s += v; ss += v*v; }
            float m = s * (1.0f/CDIM);
            float var = ss * (1.0f/CDIM) - m*m;
            mean_s[tid] = m; rstd_s[tid] = rsqrtf(var + 1e-5f);
        }
        __syncthreads();
        for (int i = tid; i < CDIM*GT_TT; i += 512) {
            int t = i % GT_TT, c = i / GT_TT;
            xs[c*GT_XS + t] = (xs[c*GT_XS + t] - mean_s[t]) * rstd_s[t] * lng[c] + lnb[c];
        }
    }

    int wc = (wid & 3) * 48;
    int wt = (wid >> 2) * 16;

    float acc[3][2][4];
    #pragma unroll
    for (int m = 0; m < 3; m++)
        #pragma unroll
        for (int n = 0; n < 2; n++)
            #pragma unroll
            for (int q = 0; q < 4; q++) acc[m][n][q] = 0.f;

    for (int kc = 0; kc < 2; kc++) {
        __syncthreads();
        STAGE_W2(wsp, DM, CDIM, W, kc*48)
        /* stage x chunk from LN'd raw smem */
        for (int i = tid; i < 24*GT_TT; i += 512) {
            int k2 = i / GT_TT, t = i % GT_TT;
            float v0 = xs[(kc*48 + 2*k2)*GT_XS + t];
            float v1 = xs[(kc*48 + 2*k2 + 1)*GT_XS + t];
            xsp[k2*XS_G + t] = bfsplit2(v0, v1);
        }
        __syncthreads();

        #pragma unroll
        for (int ks = 0; ks < 3; ks++) {
            int ksb = ks*8;
            unsigned bh[2][2], bl[2][2];
            #pragma unroll
            for (int n = 0; n < 2; n++) {
                int t = wt + n*8 + (lane>>2);
                BFRAG2(bh[n], bl[n], xsp, XS_G, ksb, t)
            }
            #pragma unroll
            for (int m = 0; m < 3; m++) {
                unsigned ah[4], al[4];
                AFRAG2(ah, al, wsp, wc + m*16 + (lane>>2), ksb)
                #pragma unroll
                for (int n = 0; n < 2; n++) {
                    mma16(acc[m][n], ah, bl[n]);
                    mma16(acc[m][n], al, bh[n]);
                    mma16(acc[m][n], ah, bh[n]);
                }
            }
        }
    }

    float* dst = (sel == 0) ? g_xin : ((sel == 1) ? g_kp : g_qp);
    float* dstb = dst + ((size_t)b*DM)*L_ + l0;
    #pragma unroll
    for (int m = 0; m < 3; m++) {
        int c = wc + m*16 + (lane>>2);
        float bv0 = bias ? bias[c] : 0.f;
        float bv1 = bias ? bias[c+8] : 0.f;
        #pragma unroll
        for (int n = 0; n < 2; n++) {
            int t = wt + n*8 + 2*(lane&3);
            float2 v0, v1;
            v0.x = acc[m][n][0] + bv0; v0.y = acc[m][n][1] + bv0;
            v1.x = acc[m][n][2] + bv1; v1.y = acc[m][n][3] + bv1;
            if (sel != 0) { v0.x = siluf(v0.x); v0.y = siluf(v0.y);
                            v1.x = siluf(v1.x); v1.y = siluf(v1.y); }
            *(float2*)&dstb[(size_t)c*L_ + t] = v0;
            *(float2*)&dstb[(size_t)(c+8)*L_ + t] = v1;
        }
    }
}

/* ============ depthwise causal conv (k=4) + silu ============ */
__global__ void __launch_bounds__(256)
conv_silu(const float* __restrict__ cw, const float* __restrict__ cb)
{
    int gid = blockIdx.x * blockDim.x + threadIdx.x;
    if (gid >= B_*DM*L_) return;
    int l  = gid % L_;
    int bd = gid / L_;
    int d  = bd % DM;
    const float* p = g_xin + (size_t)bd*L_ + l;
    float acc = cb[d] + cw[d*4+3] * p[0];
    if (l >= 1) acc = fmaf(cw[d*4+2], p[-1], acc);
    if (l >= 2) acc = fmaf(cw[d*4+1], p[-2], acc);
    if (l >= 3) acc = fmaf(cw[d*4+0], p[-3], acc);
    g_xc[gid] = siluf(acc);
}

/* ============ dtbc (fp32, proven R7 version) ============ */
#define FMA_GROUP16(j)                                                   \
    {   float4 wq = *(const float4*)&wrow[kk];                           \
        acc[0][j] = fmaf(wq.x, xq[0].x, acc[0][j]);                      \
        acc[1][j] = fmaf(wq.x, xq[0].y, acc[1][j]);                      \
        acc[2][j] = fmaf(wq.x, xq[0].z, acc[2][j]);                      \
        acc[3][j] = fmaf(wq.x, xq[0].w, acc[3][j]);                      \
        acc[0][j] = fmaf(wq.y, xq[1].x, acc[0][j]);                      \
        acc[1][j] = fmaf(wq.y, xq[1].y, acc[1][j]);                      \
        acc[2][j] = fmaf(wq.y, xq[1].z, acc[2][j]);                      \
        acc[3][j] = fmaf(wq.y, xq[1].w, acc[3][j]);                      \
        acc[0][j] = fmaf(wq.z, xq[2].x, acc[0][j]);                      \
        acc[1][j] = fmaf(wq.z, xq[2].y, acc[1][j]);                      \
        acc[2][j] = fmaf(wq.z, xq[2].z, acc[2][j]);                      \
        acc[3][j] = fmaf(wq.z, xq[2].w, acc[3][j]);                      \
        acc[0][j] = fmaf(wq.w, xq[3].x, acc[0][j]);                      \
        acc[1][j] = fmaf(wq.w, xq[3].y, acc[1][j]);                      \
        acc[2][j] = fmaf(wq.w, xq[3].z, acc[2][j]);                      \
        acc[3][j] = fmaf(wq.w, xq[3].w, acc[3][j]); }

__global__ void __launch_bounds__(512)
dtbc_kernel(const float* __restrict__ dtbc_w, const float* __restrict__ dt_w,
            const float* __restrict__ dt_b)
{
    extern __shared__ float sm[];
    float* xs   = sm;                    // 96*TTP
    float* ws   = xs + 96*TTP;           // 38*96
    float* dbl  = ws + 38*96;            // 38*TTP
    float* dtw  = dbl + 38*TTP;          // 192*6
    float* dtb  = dtw + 192*6;           // 192
    int tid = threadIdx.x;
    int tok0 = blockIdx.x * TT;
    int b = tok0 / L_, l0 = tok0 % L_;

    for (int i = tid; i < DM*RT; i += 512) dtw[i] = dt_w[i];
    for (int i = tid; i < DM;    i += 512) dtb[i] = dt_b[i];

    int tx = tid & 31, ty = tid >> 5;
    float acc[4][3];
    #pragma unroll
    for (int m = 0; m < 4; m++)
        #pragma unroll
        for (int j = 0; j < 3; j++) acc[m][j] = 0.f;

    for (int kc = 0; kc < 4; kc++) {
        const float* src = (kc < 2) ? g_xc : g_kp;
        int k0 = (kc & 1) * 96;
        __syncthreads();
        for (int i = tid; i < 96*TT; i += 512) {
            int t = i % TT, k = i / TT;
            xs[k*TTP + t] = src[((size_t)b*DM + k0 + k)*L_ + l0 + t];
        }
        for (int i = tid; i < 38*96; i += 512) {
            int c = i / 96, kk = i % 96;
            ws[i] = dtbc_w[c*384 + kc*96 + kk];
        }
        __syncthreads();
        #pragma unroll 2
        for (int kk = 0; kk < 96; kk += 4) {
            float4 xq[4];
            #pragma unroll
            for (int q = 0; q < 4; q++)
                xq[q] = *(const float4*)&xs[(kk+q)*TTP + tx*4];
            #pragma unroll
            for (int j = 0; j < 3; j++) {
                int c = ty + 16*j;
                if (c < 38) {
                    const float* wrow = &ws[c*96];
                    FMA_GROUP16(j)
                }
            }
        }
    }
    __syncthreads();
    #pragma unroll
    for (int j = 0; j < 3; j++) {
        int c = ty + 16*j;
        if (c < 38) {
            float4 v; v.x = acc[0][j]; v.y = acc[1][j]; v.z = acc[2][j]; v.w = acc[3][j];
            *(float4*)&dbl[c*TTP + tx*4] = v;
        }
    }
    __syncthreads();

    for (int i = tid; i < DM*TT; i += 512) {
        int t = i % TT, d = i / TT;
        float s = 2.0f * dtb[d];
        #pragma unroll
        for (int r = 0; r < RT; r++) s = fmaf(dbl[r*TTP + t], dtw[d*RT + r], s);
        float dl = (s > 20.f) ? s : log1pf(__expf(s));
        g_dl[((size_t)b*DM + d)*L_ + l0 + t] = dl;
    }
    for (int i = tid; i < 2*NS*TT; i += 512) {
        int t = i % TT, q = i / TT;
        float v = dbl[(RT + q)*TTP + t];
        if (q < NS) g_Bs[((size_t)b*NS + q)*L_ + l0 + t] = v;
        else        g_Cs[((size_t)b*NS + (q-NS))*L_ + l0 + t] = v;
    }
}

/* ==== gate: z = silu(cat(xc,qp) @ gate_w^T + b), bf16 3-term split ====
   64 tokens, K=384 in 8 chunks of 48. */
__global__ void __launch_bounds__(512, 2)
gate_bf(const float* __restrict__ gate_w, const float* __restrict__ gate_b)
{
    extern __shared__ float sm[];
    uint2* wsp = (uint2*)sm;             // 192*WSTR2
    uint2* xsp = wsp + 192*WSTR2;        // 24*XS_G
    int tid = threadIdx.x, lane = tid & 31, wid = tid >> 5;
    int tok0 = blockIdx.x * GT_TT;
    int b = tok0 / L_, l0 = tok0 % L_;
    int wc = (wid & 3) * 48;
    int wt = (wid >> 2) * 16;

    float acc[3][2][4];
    #pragma unroll
    for (int m = 0; m < 3; m++)
        #pragma unroll
        for (int n = 0; n < 2; n++)
            #pragma unroll
            for (int q = 0; q < 4; q++) acc[m][n][q] = 0.f;

    for (int kc = 0; kc < 8; kc++) {
        const float* src = (kc < 4) ? g_xc : g_qp;
        int ch0 = (kc & 3) * 48;
        __syncthreads();
        STAGE_W2(wsp, DM, 384, gate_w, kc*48)
        for (int i = tid; i < 24*GT_TT; i += 512) {
            int k2 = i / GT_TT, t = i % GT_TT;
            float v0 = src[((size_t)b*DM + ch0 + 2*k2)*L_ + l0 + t];
            float v1 = src[((size_t)b*DM + ch0 + 2*k2 + 1)*L_ + l0 + t];
            xsp[k2*XS_G + t] = bfsplit2(v0, v1);
        }
        __syncthreads();

        #pragma unroll
        for (int ks = 0; ks < 3; ks++) {
            int ksb = ks*8;
            unsigned bh[2][2], bl[2][2];
            #pragma unroll
            for (int n = 0; n < 2; n++) {
                int t = wt + n*8 + (lane>>2);
                BFRAG2(bh[n], bl[n], xsp, XS_G, ksb, t)
            }
            #pragma unroll
            for (int m = 0; m < 3; m++) {
                unsigned ah[4], al[4];
                AFRAG2(ah, al, wsp, wc + m*16 + (lane>>2), ksb)
                #pragma unroll
                for (int n = 0; n < 2; n++) {
                    mma16(acc[m][n], ah, bl[n]);
                    mma16(acc[m][n], al, bh[n]);
                    mma16(acc[m][n], ah, bh[n]);
                }
            }
        }
    }

    float* dstb = g_z + ((size_t)b*DM)*L_ + l0;
    #pragma unroll
    for (int m = 0; m < 3; m++) {
        int c = wc + m*16 + (lane>>2);
        float bv0 = gate_b[c], bv1 = gate_b[c+8];
        #pragma unroll
        for (int n = 0; n < 2; n++) {
            int t = wt + n*8 + 2*(lane&3);
            float2 v0, v1;
            v0.x = siluf(acc[m][n][0] + bv0); v0.y = siluf(acc[m][n][1] + bv0);
            v1.x = siluf(acc[m][n][2] + bv1); v1.y = siluf(acc[m][n][3] + bv1);
            *(float2*)&dstb[(size_t)c*L_ + t] = v0;
            *(float2*)&dstb[(size_t)(c+8)*L_ + t] = v1;
        }
    }
}

/* ============ chunked selective scan (unchanged) ============ */
__global__ void __launch_bounds__(256)
scan1(const float* __restrict__ A_log)
{
    __shared__ float dls[16*97], xcs[16*97], bs[16*97];
    int b = blockIdx.z, ch = blockIdx.y, dblk = blockIdx.x;
    int d0 = dblk*16;
    int tid = threadIdx.x;
    for (int i = tid; i < 16*G_; i += 256) {
        int r = i / G_, t = i % G_;
        dls[r*97+t] = g_dl[((size_t)b*DM + d0 + r)*L_ + ch*G_ + t];
        xcs[r*97+t] = g_xc[((size_t)b*DM + d0 + r)*L_ + ch*G_ + t];
        bs [r*97+t] = g_Bs[((size_t)b*NS + r)*L_ + ch*G_ + t];
    }
    __syncthreads();
    int n = tid & 15, dloc = tid >> 4;
    int d = d0 + dloc;
    float A = -__expf(A_log[d*NS + n]);
    float h = 0.f, S = 0.f;
    #pragma unroll 4
    for (int t = 0; t < G_; t++) {
        float dl = dls[dloc*97+t];
        float a = __expf(dl * A);
        S += dl;
        h = fmaf(a, h, dl * xcs[dloc*97+t] * bs[n*97+t]);
    }
    size_t o = (((size_t)(b*NCH + ch))*DM + d)*NS + n;
    g_P[o] = __expf(A * S); g_Hl[o] = h;
}

__global__ void __launch_bounds__(256)
scan2()
{
    int idx = blockIdx.x * blockDim.x + threadIdx.x;
    if (idx >= B_*DM*NS) return;
    int b = idx / (DM*NS);
    int dn = idx % (DM*NS);
    float h = 0.f;
    for (int ch = 0; ch < NCH; ch++) {
        size_t o = ((size_t)(b*NCH + ch))*(DM*NS) + dn;
        g_Hi[o] = h;
        h = fmaf(g_P[o], h, g_Hl[o]);
    }
}

__global__ void __launch_bounds__(256)
scan3(const float* __restrict__ A_log, const float* __restrict__ Dp)
{
    __shared__ float dls[16*97], xcs[16*97], bs[16*97], cs[16*97], zs[16*97], ys[16*97];
    int b = blockIdx.z, ch = blockIdx.y, dblk = blockIdx.x;
    int d0 = dblk*16;
    int tid = threadIdx.x;
    for (int i = tid; i < 16*G_; i += 256) {
        int r = i / G_, t = i % G_;
        size_t db = ((size_t)b*DM + d0 + r)*L_ + ch*G_ + t;
        size_t nb = ((size_t)b*NS + r)*L_ + ch*G_ + t;
        dls[r*97+t] = g_dl[db];
        xcs[r*97+t] = g_xc[db];
        zs [r*97+t] = g_z [db];
        bs [r*97+t] = g_Bs[nb];
        cs [r*97+t] = g_Cs[nb];
    }
    __syncthreads();
    int n = tid & 15, dloc = tid >> 4;
    int d = d0 + dloc;
    float A = -__expf(A_log[d*NS + n]);
    size_t o = (((size_t)(b*NCH + ch))*DM + d)*NS + n;
    float h = g_Hi[o];
    float Dd = Dp[d];
    for (int t = 0; t < G_; t++) {
        float dl = dls[dloc*97+t];
        float u  = xcs[dloc*97+t];
        float a = __expf(dl * A);
        h = fmaf(a, h, dl * u * bs[n*97+t]);
        float v = h * cs[n*97+t];
        v += __shfl_xor_sync(0xffffffffu, v, 1);
        v += __shfl_xor_sync(0xffffffffu, v, 2);
        v += __shfl_xor_sync(0xffffffffu, v, 4);
        v += __shfl_xor_sync(0xffffffffu, v, 8);
        if (n == 0)
            ys[dloc*97+t] = (v + u * Dd) * zs[dloc*97+t];
    }
    __syncthreads();
    for (int i = tid; i < 16*G_; i += 256) {
        int r = i / G_, t = i % G_;
        g_y[((size_t)b*DM + d0 + r)*L_ + ch*G_ + t] = ys[r*97+t];
    }
}

/* ==== out projection: out = y @ out_w^T, bf16 3-term split ====
   128 tokens, N=96, K=192 in 4 chunks of 48. 16 warps = 2 ch x 8 tok. */
__global__ void __launch_bounds__(512, 2)
gemm_out_bf(const float* __restrict__ out_w, float* __restrict__ out)
{
    extern __shared__ float sm[];
    uint2* wsp = (uint2*)sm;             // 96*WSTR2
    uint2* xsp = wsp + 96*WSTR2;         // 24*XS_O
    int tid = threadIdx.x, lane = tid & 31, wid = tid >> 5;
    int tok0 = blockIdx.x * TT;
    int b = tok0 / L_, l0 = tok0 % L_;
    int wc = (wid & 1) * 48;
    int wt = (wid >> 1) * 16;

    float acc[3][2][4];
    #pragma unroll
    for (int m = 0; m < 3; m++)
        #pragma unroll
        for (int n = 0; n < 2; n++)
            #pragma unroll
            for (int q = 0; q < 4; q++) acc[m][n][q] = 0.f;

    for (int kc = 0; kc < 4; kc++) {
        __syncthreads();
        STAGE_W2(wsp, CDIM, DM, out_w, kc*48)
        for (int i = tid; i < 24*TT; i += 512) {
            int k2 = i / TT, t = i % TT;
            float v0 = g_y[((size_t)b*DM + kc*48 + 2*k2)*L_ + l0 + t];
            float v1 = g_y[((size_t)b*DM + kc*48 + 2*k2 + 1)*L_ + l0 + t];
            xsp[k2*XS_O + t] = bfsplit2(v0, v1);
        }
        __syncthreads();

        #pragma unroll
        for (int ks = 0; ks < 3; ks++) {
            int ksb = ks*8;
            unsigned bh[2][2], bl[2][2];
            #pragma unroll
            for (int n = 0; n < 2; n++) {
                int t = wt + n*8 + (lane>>2);
                BFRAG2(bh[n], bl[n], xsp, XS_O, ksb, t)
            }
            #pragma unroll
            for (int m = 0; m < 3; m++) {
                unsigned ah[4], al[4];
                AFRAG2(ah, al, wsp, wc + m*16 + (lane>>2), ksb)
                #pragma unroll
                for (int n = 0; n < 2; n++) {
                    mma16(acc[m][n], ah, bl[n]);
                    mma16(acc[m][n], al, bh[n]);
                    mma16(acc[m][n], ah, bh[n]);
                }
            }
        }
    }

    float* ob = out + ((size_t)b*CDIM)*L_ + l0;
    #pragma unroll
    for (int m = 0; m < 3; m++) {
        int c = wc + m*16 + (lane>>2);
        #pragma unroll
        for (int n = 0; n < 2; n++) {
            int t = wt + n*8 + 2*(lane&3);
            float2 v0, v1;
            v0.x = acc[m][n][0]; v0.y = acc[m][n][1];
            v1.x = acc[m][n][2]; v1.y = acc[m][n][3];
            *(float2*)&ob[(size_t)c*L_ + t] = v0;
            *(float2*)&ob[(size_t)(c+8)*L_ + t] = v1;
        }
    }
}

/* ============ host launcher ============ */
extern "C" void kernel_launch(void* const* d_in, const int* in_sizes, int n_in,
                              void* d_out, int out_size)
{
    const float* x         = (const float*)d_in[0];
    const float* Kin       = (const float*)d_in[1];
    const float* Qin       = (const float*)d_in[2];
    const float* in_proj_w = (const float*)d_in[3];
    const float* conv_w    = (const float*)d_in[4];
    const float* conv_b    = (const float*)d_in[5];
    const float* k_ln_g    = (const float*)d_in[6];
    const float* k_ln_b    = (const float*)d_in[7];
    const float* k_w       = (const float*)d_in[8];
    const float* k_b       = (const float*)d_in[9];
    const float* q_ln_g    = (const float*)d_in[10];
    const float* q_ln_b    = (const float*)d_in[11];
    const float* q_w       = (const float*)d_in[12];
    const float* q_b       = (const float*)d_in[13];
    const float* dtbc_w    = (const float*)d_in[14];
    const float* dt_w      = (const float*)d_in[15];
    const float* dt_b      = (const float*)d_in[16];
    const float* gate_w    = (const float*)d_in[17];
    const float* gate_b    = (const float*)d_in[18];
    const float* A_log     = (const float*)d_in[19];
    const float* Dp        = (const float*)d_in[20];
    const float* out_w     = (const float*)d_in[21];
    float* out = (float*)d_out;

    const int SMEM_G3 = (96*GT_XS + 2*(192*WSTR2 + 24*XS_G) + 128) * 4;  /* ~84 KB */
    const int SMEM_D  = (96*TTP + 38*96 + 38*TTP + 192*6 + 192) * 4;     /* ~89 KB */
    const int SMEM_GT = (2*(192*WSTR2 + 24*XS_G)) * 4;                   /* ~56 KB */
    const int SMEM_OT = (2*(96*WSTR2 + 24*XS_O)) * 4;                    /* ~47 KB */

    cudaFuncSetAttribute(gemm3_bf,    cudaFuncAttributeMaxDynamicSharedMemorySize, SMEM_G3);
    cudaFuncSetAttribute(dtbc_kernel, cudaFuncAttributeMaxDynamicSharedMemorySize, SMEM_D);
    cudaFuncSetAttribute(gate_bf,     cudaFuncAttributeMaxDynamicSharedMemorySize, SMEM_GT);
    cudaFuncSetAttribute(gemm_out_bf, cudaFuncAttributeMaxDynamicSharedMemorySize, SMEM_OT);

    /* 1. fused in_proj + K + Q (bf16 split tensor cores, LN fused) */
    gemm3_bf<<<dim3(BL/GT_TT,3), 512, SMEM_G3>>>(x, Kin, Qin, in_proj_w,
        k_w, k_b, k_ln_g, k_ln_b, q_w, q_b, q_ln_g, q_ln_b);
    /* 2. depthwise conv + silu */
    conv_silu<<<(B_*DM*L_)/256, 256>>>(conv_w, conv_b);
    /* 3. dtbc -> delta, B, C (fp32) */
    dtbc_kernel<<<NTILE, 512, SMEM_D>>>(dtbc_w, dt_w, dt_b);
    /* 4. gate -> silu(z) (bf16 split tensor cores) */
    gate_bf<<<BL/GT_TT, 512, SMEM_GT>>>(gate_w, gate_b);
    /* 5-7. chunked selective scan */
    scan1<<<dim3(DM/16, NCH, B_), 256>>>(A_log);
    scan2<<<(B_*DM*NS)/256, 256>>>();
    scan3<<<dim3(DM/16, NCH, B_), 256>>>(A_log, Dp);
    /* 8. output projection (bf16 split tensor cores) */
    gemm_out_bf<<<NTILE, 512, SMEM_OT>>>(out_w, out);
}

// round 16
// speedup vs baseline: 1.1571x; 1.0156x over previous
#include <cuda_runtime.h>
#include <cuda_bf16.h>

#define B_    4
#define CDIM  96
#define L_    9216
#define DM    192
#define NS    16
#define RT    6
#define BL    (B_*L_)
#define TT    128         /* dtbc / out token tile */
#define NTILE (BL/TT)     /* 288 */
#define G_    96
#define NCH   (L_/G_)     /* 96 */
#define TTP   132         /* fp32 GEMM xs stride */

/* bf16-split kernels */
#define GT_TT  64
#define GT_XS  72
#define WSTR2  28         /* W smem stride in uint2 */
#define XS_G   68         /* X smem stride in uint2 (gate/gemm3) */
#define XS_O   132        /* X smem stride in uint2 (out) */

/* ---- scratch ---- */
__device__ float g_xin[(size_t)B_*DM*L_];
__device__ float g_xc [(size_t)B_*DM*L_];
__device__ float g_kp [(size_t)B_*DM*L_];
__device__ float g_qp [(size_t)B_*DM*L_];
__device__ float g_dl [(size_t)B_*DM*L_];
__device__ float g_z  [(size_t)B_*DM*L_];
__device__ float g_Bs [(size_t)B_*NS*L_];
__device__ float g_Cs [(size_t)B_*NS*L_];
__device__ float g_P  [(size_t)B_*NCH*DM*NS];
__device__ float g_Hl [(size_t)B_*NCH*DM*NS];
__device__ float g_Hi [(size_t)B_*NCH*DM*NS];
/* pre-split (hi,lo) bf16 pairs, channel-pair-major activations */
__device__ uint2 g_xc2[(size_t)B_*(DM/2)*L_];
__device__ uint2 g_qp2[(size_t)B_*(DM/2)*L_];
__device__ uint2 g_y2 [(size_t)B_*(DM/2)*L_];
/* pre-split weights */
__device__ uint2 g_wg2[(size_t)DM*192];       /* gate_w  [c][k2], K=384 */
__device__ uint2 g_w32[(size_t)3*DM*48];      /* in/k/q  [sel][c][k2], K=96 */
__device__ uint2 g_wo2[(size_t)CDIM*96];      /* out_w   [c][k2], K=192 */

__device__ __forceinline__ float siluf(float v) { return v / (1.0f + __expf(-v)); }

__device__ __forceinline__ uint2 bfsplit2(float v0, float v1) {
    __nv_bfloat16 h0 = __float2bfloat16(v0);
    __nv_bfloat16 h1 = __float2bfloat16(v1);
    __nv_bfloat16 l0 = __float2bfloat16(v0 - __bfloat162float(h0));
    __nv_bfloat16 l1 = __float2bfloat16(v1 - __bfloat162float(h1));
    uint2 r;
    r.x = ((unsigned)__bfloat16_as_ushort(h1) << 16) | __bfloat16_as_ushort(h0);
    r.y = ((unsigned)__bfloat16_as_ushort(l1) << 16) | __bfloat16_as_ushort(l0);
    return r;
}

__device__ __forceinline__ void mma16(float* d, const unsigned* a, const unsigned* b) {
    asm volatile("mma.sync.aligned.m16n8k16.row.col.f32.bf16.bf16.f32 "
        "{%0,%1,%2,%3}, {%4,%5,%6,%7}, {%8,%9}, {%0,%1,%2,%3};"
        : "+f"(d[0]), "+f"(d[1]), "+f"(d[2]), "+f"(d[3])
        : "r"(a[0]), "r"(a[1]), "r"(a[2]), "r"(a[3]), "r"(b[0]), "r"(b[1]));
}

#define AFRAG2(AH, AL_, Wp, c, ksb) {                                     \
    uint2 q0_ = (Wp)[(c)*WSTR2 + (ksb) + (lane&3)];                       \
    uint2 q1_ = (Wp)[((c)+8)*WSTR2 + (ksb) + (lane&3)];                   \
    uint2 q2_ = (Wp)[(c)*WSTR2 + (ksb) + (lane&3) + 4];                   \
    uint2 q3_ = (Wp)[((c)+8)*WSTR2 + (ksb) + (lane&3) + 4];               \
    AH[0]=q0_.x; AH[1]=q1_.x; AH[2]=q2_.x; AH[3]=q3_.x;                   \
    AL_[0]=q0_.y; AL_[1]=q1_.y; AL_[2]=q2_.y; AL_[3]=q3_.y; }

#define BFRAG2(BH, BL_, Xp, XSTR, ksb, t) {                               \
    uint2 q0_ = (Xp)[((ksb) + (lane&3))*(XSTR) + (t)];                    \
    uint2 q1_ = (Xp)[((ksb) + (lane&3) + 4)*(XSTR) + (t)];                \
    BH[0]=q0_.x; BH[1]=q1_.x; BL_[0]=q0_.y; BL_[1]=q1_.y; }

/* ============ weight pre-split (runs once per launch, tiny) ============ */
__global__ void __launch_bounds__(512)
prep_w(const float* __restrict__ in_w, const float* __restrict__ k_w,
       const float* __restrict__ q_w, const float* __restrict__ gate_w,
       const float* __restrict__ out_w)
{
    int i = blockIdx.x*512 + threadIdx.x;
    if (i < DM*192) {
        int c = i / 192, k2 = i % 192;
        g_wg2[i] = bfsplit2(gate_w[(size_t)c*384 + 2*k2], gate_w[(size_t)c*384 + 2*k2 + 1]);
    } else if (i < DM*192 + 3*DM*48) {
        int j = i - DM*192;
        int s = j / (DM*48), r = j % (DM*48);
        int c = r / 48, k2 = r % 48;
        const float* W = (s==0) ? in_w : (s==1 ? k_w : q_w);
        g_w32[j] = bfsplit2(W[(size_t)c*96 + 2*k2], W[(size_t)c*96 + 2*k2 + 1]);
    } else if (i < DM*192 + 3*DM*48 + CDIM*96) {
        int j = i - (DM*192 + 3*DM*48);
        int c = j / 96, k2 = j % 96;
        g_wo2[j] = bfsplit2(out_w[(size_t)c*192 + 2*k2], out_w[(size_t)c*192 + 2*k2 + 1]);
    }
}

/* ==== fused 3x GEMM (in_proj / K / Q), LN fused, bf16 3-term split ==== */
__global__ void __launch_bounds__(512, 2)
gemm3_bf(const float* __restrict__ x, const float* __restrict__ Kin,
         const float* __restrict__ Qin,
         const float* __restrict__ k_b, const float* __restrict__ k_ln_g,
         const float* __restrict__ k_ln_b, const float* __restrict__ q_b,
         const float* __restrict__ q_ln_g, const float* __restrict__ q_ln_b)
{
    extern __shared__ float sm[];
    float* xs = sm;                              // 96*GT_XS raw
    uint2* wsp = (uint2*)(sm + 96*GT_XS);        // 192*WSTR2
    uint2* xsp = wsp + 192*WSTR2;                // 24*XS_G
    float* mean_s = (float*)(xsp + 24*XS_G);
    float* rstd_s = mean_s + 64;

    int sel = blockIdx.y;
    const float* src  = (sel==0) ? x : (sel==1 ? Kin : Qin);
    const float* bias = (sel==0) ? 0 : (sel==1 ? k_b : q_b);
    const float* lng  = (sel==1) ? k_ln_g : q_ln_g;
    const float* lnb  = (sel==1) ? k_ln_b : q_ln_b;
    const uint2* wsrc = g_w32 + (size_t)sel*DM*48;

    int tid = threadIdx.x, lane = tid & 31, wid = tid >> 5;
    int tok0 = blockIdx.x * GT_TT;
    int b = tok0 / L_, l0 = tok0 % L_;
    const float* srcb = src + ((size_t)b*CDIM)*L_ + l0;

    for (int i = tid; i < CDIM*GT_TT; i += 512) {
        int t = i % GT_TT, k = i / GT_TT;
        xs[k*GT_XS + t] = srcb[(size_t)k*L_ + t];
    }
    __syncthreads();

    if (sel != 0) {
        if (tid < GT_TT) {
            float s = 0.f, ss = 0.f;
            for (int c = 0; c < CDIM; c++) { float v = xs[c*GT_XS + tid]; s += v; ss += v*v; }
            float m = s * (1.0f/CDIM);
            float var = ss * (1.0f/CDIM) - m*m;
            mean_s[tid] = m; rstd_s[tid] = rsqrtf(var + 1e-5f);
        }
        __syncthreads();
        for (int i = tid; i < CDIM*GT_TT; i += 512) {
            int t = i % GT_TT, c = i / GT_TT;
            xs[c*GT_XS + t] = (xs[c*GT_XS + t] - mean_s[t]) * rstd_s[t] * lng[c] + lnb[c];
        }
    }

    int wc = (wid & 3) * 48;
    int wt = (wid >> 2) * 16;

    float acc[3][2][4];
    #pragma unroll
    for (int m = 0; m < 3; m++)
        #pragma unroll
        for (int n = 0; n < 2; n++)
            #pragma unroll
            for (int q = 0; q < 4; q++) acc[m][n][q] = 0.f;

    for (int kc = 0; kc < 2; kc++) {
        __syncthreads();
        for (int i = tid; i < DM*24; i += 512) {
            int c = i / 24, k2 = i % 24;
            wsp[c*WSTR2 + k2] = wsrc[(size_t)c*48 + kc*24 + k2];
        }
        for (int i = tid; i < 24*GT_TT; i += 512) {
            int k2 = i / GT_TT, t = i % GT_TT;
            float v0 = xs[(kc*48 + 2*k2)*GT_XS + t];
            float v1 = xs[(kc*48 + 2*k2 + 1)*GT_XS + t];
            xsp[k2*XS_G + t] = bfsplit2(v0, v1);
        }
        __syncthreads();

        #pragma unroll
        for (int ks = 0; ks < 3; ks++) {
            int ksb = ks*8;
            unsigned bh[2][2], bl[2][2];
            #pragma unroll
            for (int n = 0; n < 2; n++) {
                int t = wt + n*8 + (lane>>2);
                BFRAG2(bh[n], bl[n], xsp, XS_G, ksb, t)
            }
            #pragma unroll
            for (int m = 0; m < 3; m++) {
                unsigned ah[4], al[4];
                AFRAG2(ah, al, wsp, wc + m*16 + (lane>>2), ksb)
                #pragma unroll
                for (int n = 0; n < 2; n++) {
                    mma16(acc[m][n], ah, bl[n]);
                    mma16(acc[m][n], al, bh[n]);
                    mma16(acc[m][n], ah, bh[n]);
                }
            }
        }
    }

    float* dst = (sel == 0) ? g_xin : ((sel == 1) ? g_kp : g_qp);
    float* dstb = dst + ((size_t)b*DM)*L_ + l0;
    #pragma unroll
    for (int m = 0; m < 3; m++) {
        int c = wc + m*16 + (lane>>2);
        float bv0 = bias ? bias[c] : 0.f;
        float bv1 = bias ? bias[c+8] : 0.f;
        #pragma unroll
        for (int n = 0; n < 2; n++) {
            int t = wt + n*8 + 2*(lane&3);
            float2 v0, v1;
            v0.x = acc[m][n][0] + bv0; v0.y = acc[m][n][1] + bv0;
            v1.x = acc[m][n][2] + bv1; v1.y = acc[m][n][3] + bv1;
            if (sel != 0) { v0.x = siluf(v0.x); v0.y = siluf(v0.y);
                            v1.x = siluf(v1.x); v1.y = siluf(v1.y); }
            *(float2*)&dstb[(size_t)c*L_ + t] = v0;
            *(float2*)&dstb[(size_t)(c+8)*L_ + t] = v1;
        }
    }
}

/* ============ conv (2 channels/thread) + silu, writes fp32 + split ============ */
__global__ void __launch_bounds__(256)
conv_silu(const float* __restrict__ cw, const float* __restrict__ cb)
{
    int gid = blockIdx.x * blockDim.x + threadIdx.x;   // over B*(DM/2)*L
    if (gid >= B_*(DM/2)*L_) return;
    int l   = gid % L_;
    int bd2 = gid / L_;
    int d2  = bd2 % (DM/2);
    int b   = bd2 / (DM/2);
    int d   = 2*d2;
    const float* p0 = g_xin + (((size_t)b*DM + d)*L_) + l;
    const float* p1 = p0 + L_;
    float a0 = cb[d]   + cw[d*4+3]     * p0[0];
    float a1 = cb[d+1] + cw[(d+1)*4+3] * p1[0];
    if (l >= 1) { a0 = fmaf(cw[d*4+2], p0[-1], a0); a1 = fmaf(cw[(d+1)*4+2], p1[-1], a1); }
    if (l >= 2) { a0 = fmaf(cw[d*4+1], p0[-2], a0); a1 = fmaf(cw[(d+1)*4+1], p1[-2], a1); }
    if (l >= 3) { a0 = fmaf(cw[d*4+0], p0[-3], a0); a1 = fmaf(cw[(d+1)*4+0], p1[-3], a1); }
    float s0 = siluf(a0), s1 = siluf(a1);
    g_xc[((size_t)b*DM + d)*L_ + l]     = s0;
    g_xc[((size_t)b*DM + d + 1)*L_ + l] = s1;
    g_xc2[((size_t)b*(DM/2) + d2)*L_ + l] = bfsplit2(s0, s1);
}

/* ============ split Q path into channel-pair uint2 ============ */
__global__ void __launch_bounds__(256)
split_qp()
{
    int gid = blockIdx.x * blockDim.x + threadIdx.x;
    if (gid >= B_*(DM/2)*L_) return;
    int l   = gid % L_;
    int bd2 = gid / L_;
    int d2  = bd2 % (DM/2);
    int b   = bd2 / (DM/2);
    float v0 = g_qp[((size_t)b*DM + 2*d2)*L_ + l];
    float v1 = g_qp[((size_t)b*DM + 2*d2 + 1)*L_ + l];
    g_qp2[((size_t)b*(DM/2) + d2)*L_ + l] = bfsplit2(v0, v1);
}

/* ============ dtbc (fp32, proven R7 version) ============ */
#define FMA_GROUP16(j)                                                   \
    {   float4 wq = *(const float4*)&wrow[kk];                           \
        acc[0][j] = fmaf(wq.x, xq[0].x, acc[0][j]);                      \
        acc[1][j] = fmaf(wq.x, xq[0].y, acc[1][j]);                      \
        acc[2][j] = fmaf(wq.x, xq[0].z, acc[2][j]);                      \
        acc[3][j] = fmaf(wq.x, xq[0].w, acc[3][j]);                      \
        acc[0][j] = fmaf(wq.y, xq[1].x, acc[0][j]);                      \
        acc[1][j] = fmaf(wq.y, xq[1].y, acc[1][j]);                      \
        acc[2][j] = fmaf(wq.y, xq[1].z, acc[2][j]);                      \
        acc[3][j] = fmaf(wq.y, xq[1].w, acc[3][j]);                      \
        acc[0][j] = fmaf(wq.z, xq[2].x, acc[0][j]);                      \
        acc[1][j] = fmaf(wq.z, xq[2].y, acc[1][j]);                      \
        acc[2][j] = fmaf(wq.z, xq[2].z, acc[2][j]);                      \
        acc[3][j] = fmaf(wq.z, xq[2].w, acc[3][j]);                      \
        acc[0][j] = fmaf(wq.w, xq[3].x, acc[0][j]);                      \
        acc[1][j] = fmaf(wq.w, xq[3].y, acc[1][j]);                      \
        acc[2][j] = fmaf(wq.w, xq[3].z, acc[2][j]);                      \
        acc[3][j] = fmaf(wq.w, xq[3].w, acc[3][j]); }

__global__ void __launch_bounds__(512)
dtbc_kernel(const float* __restrict__ dtbc_w, const float* __restrict__ dt_w,
            const float* __restrict__ dt_b)
{
    extern __shared__ float sm[];
    float* xs   = sm;
    float* ws   = xs + 96*TTP;
    float* dbl  = ws + 38*96;
    float* dtw  = dbl + 38*TTP;
    float* dtb  = dtw + 192*6;
    int tid = threadIdx.x;
    int tok0 = blockIdx.x * TT;
    int b = tok0 / L_, l0 = tok0 % L_;

    for (int i = tid; i < DM*RT; i += 512) dtw[i] = dt_w[i];
    for (int i = tid; i < DM;    i += 512) dtb[i] = dt_b[i];

    int tx = tid & 31, ty = tid >> 5;
    float acc[4][3];
    #pragma unroll
    for (int m = 0; m < 4; m++)
        #pragma unroll
        for (int j = 0; j < 3; j++) acc[m][j] = 0.f;

    for (int kc = 0; kc < 4; kc++) {
        const float* src = (kc < 2) ? g_xc : g_kp;
        int k0 = (kc & 1) * 96;
        __syncthreads();
        for (int i = tid; i < 96*TT; i += 512) {
            int t = i % TT, k = i / TT;
            xs[k*TTP + t] = src[((size_t)b*DM + k0 + k)*L_ + l0 + t];
        }
        for (int i = tid; i < 38*96; i += 512) {
            int c = i / 96, kk = i % 96;
            ws[i] = dtbc_w[c*384 + kc*96 + kk];
        }
        __syncthreads();
        #pragma unroll 2
        for (int kk = 0; kk < 96; kk += 4) {
            float4 xq[4];
            #pragma unroll
            for (int q = 0; q < 4; q++)
                xq[q] = *(const float4*)&xs[(kk+q)*TTP + tx*4];
            #pragma unroll
            for (int j = 0; j < 3; j++) {
                int c = ty + 16*j;
                if (c < 38) {
                    const float* wrow = &ws[c*96];
                    FMA_GROUP16(j)
                }
            }
        }
    }
    __syncthreads();
    #pragma unroll
    for (int j = 0; j < 3; j++) {
        int c = ty + 16*j;
        if (c < 38) {
            float4 v; v.x = acc[0][j]; v.y = acc[1][j]; v.z = acc[2][j]; v.w = acc[3][j];
            *(float4*)&dbl[c*TTP + tx*4] = v;
        }
    }
    __syncthreads();

    for (int i = tid; i < DM*TT; i += 512) {
        int t = i % TT, d = i / TT;
        float s = 2.0f * dtb[d];
        #pragma unroll
        for (int r = 0; r < RT; r++) s = fmaf(dbl[r*TTP + t], dtw[d*RT + r], s);
        float dl = (s > 20.f) ? s : log1pf(__expf(s));
        g_dl[((size_t)b*DM + d)*L_ + l0 + t] = dl;
    }
    for (int i = tid; i < 2*NS*TT; i += 512) {
        int t = i % TT, q = i / TT;
        float v = dbl[(RT + q)*TTP + t];
        if (q < NS) g_Bs[((size_t)b*NS + q)*L_ + l0 + t] = v;
        else        g_Cs[((size_t)b*NS + (q-NS))*L_ + l0 + t] = v;
    }
}

/* ==== gate: z = silu(cat(xc,qp) @ gate_w^T + b), pure-copy staging ==== */
__global__ void __launch_bounds__(512, 2)
gate_bf(const float* __restrict__ gate_b)
{
    extern __shared__ float sm[];
    uint2* wsp = (uint2*)sm;             // 192*WSTR2
    uint2* xsp = wsp + 192*WSTR2;        // 24*XS_G
    int tid = threadIdx.x, lane = tid & 31, wid = tid >> 5;
    int tok0 = blockIdx.x * GT_TT;
    int b = tok0 / L_, l0 = tok0 % L_;
    int wc = (wid & 3) * 48;
    int wt = (wid >> 2) * 16;

    float acc[3][2][4];
    #pragma unroll
    for (int m = 0; m < 3; m++)
        #pragma unroll
        for (int n = 0; n < 2; n++)
            #pragma unroll
            for (int q = 0; q < 4; q++) acc[m][n][q] = 0.f;

    for (int kc = 0; kc < 8; kc++) {
        const uint2* src2 = (kc < 4) ? g_xc2 : g_qp2;
        int ch2 = (kc & 3) * 24;
        __syncthreads();
        for (int i = tid; i < DM*24; i += 512) {
            int c = i / 24, k2 = i % 24;
            wsp[c*WSTR2 + k2] = g_wg2[(size_t)c*192 + kc*24 + k2];
        }
        for (int i = tid; i < 24*GT_TT; i += 512) {
            int k2 = i / GT_TT, t = i % GT_TT;
            xsp[k2*XS_G + t] = src2[((size_t)b*(DM/2) + ch2 + k2)*L_ + l0 + t];
        }
        __syncthreads();

        #pragma unroll
        for (int ks = 0; ks < 3; ks++) {
            int ksb = ks*8;
            unsigned bh[2][2], bl[2][2];
            #pragma unroll
            for (int n = 0; n < 2; n++) {
                int t = wt + n*8 + (lane>>2);
                BFRAG2(bh[n], bl[n], xsp, XS_G, ksb, t)
            }
            #pragma unroll
            for (int m = 0; m < 3; m++) {
                unsigned ah[4], al[4];
                AFRAG2(ah, al, wsp, wc + m*16 + (lane>>2), ksb)
                #pragma unroll
                for (int n = 0; n < 2; n++) {
                    mma16(acc[m][n], ah, bl[n]);
                    mma16(acc[m][n], al, bh[n]);
                    mma16(acc[m][n], ah, bh[n]);
                }
            }
        }
    }

    float* dstb = g_z + ((size_t)b*DM)*L_ + l0;
    #pragma unroll
    for (int m = 0; m < 3; m++) {
        int c = wc + m*16 + (lane>>2);
        float bv0 = gate_b[c], bv1 = gate_b[c+8];
        #pragma unroll
        for (int n = 0; n < 2; n++) {
            int t = wt + n*8 + 2*(lane&3);
            float2 v0, v1;
            v0.x = siluf(acc[m][n][0] + bv0); v0.y = siluf(acc[m][n][1] + bv0);
            v1.x = siluf(acc[m][n][2] + bv1); v1.y = siluf(acc[m][n][3] + bv1);
            *(float2*)&dstb[(size_t)c*L_ + t] = v0;
            *(float2*)&dstb[(size_t)(c+8)*L_ + t] = v1;
        }
    }
}

/* ============ chunked selective scan ============ */
__global__ void __launch_bounds__(256)
scan1(const float* __restrict__ A_log)
{
    __shared__ float dls[16*97], xcs[16*97], bs[16*97];
    int b = blockIdx.z, ch = blockIdx.y, dblk = blockIdx.x;
    int d0 = dblk*16;
    int tid = threadIdx.x;
    for (int i = tid; i < 16*G_; i += 256) {
        int r = i / G_, t = i % G_;
        dls[r*97+t] = g_dl[((size_t)b*DM + d0 + r)*L_ + ch*G_ + t];
        xcs[r*97+t] = g_xc[((size_t)b*DM + d0 + r)*L_ + ch*G_ + t];
        bs [r*97+t] = g_Bs[((size_t)b*NS + r)*L_ + ch*G_ + t];
    }
    __syncthreads();
    int n = tid & 15, dloc = tid >> 4;
    int d = d0 + dloc;
    float A = -__expf(A_log[d*NS + n]);
    float h = 0.f, S = 0.f;
    #pragma unroll 4
    for (int t = 0; t < G_; t++) {
        float dl = dls[dloc*97+t];
        float a = __expf(dl * A);
        S += dl;
        h = fmaf(a, h, dl * xcs[dloc*97+t] * bs[n*97+t]);
    }
    size_t o = (((size_t)(b*NCH + ch))*DM + d)*NS + n;
    g_P[o] = __expf(A * S); g_Hl[o] = h;
}

__global__ void __launch_bounds__(256)
scan2()
{
    int idx = blockIdx.x * blockDim.x + threadIdx.x;
    if (idx >= B_*DM*NS) return;
    int b = idx / (DM*NS);
    int dn = idx % (DM*NS);
    float h = 0.f;
    for (int ch = 0; ch < NCH; ch++) {
        size_t o = ((size_t)(b*NCH + ch))*(DM*NS) + dn;
        g_Hi[o] = h;
        h = fmaf(g_P[o], h, g_Hl[o]);
    }
}

__global__ void __launch_bounds__(256)
scan3(const float* __restrict__ A_log, const float* __restrict__ Dp)
{
    __shared__ float dls[16*97], xcs[16*97], bs[16*97], cs[16*97], zs[16*97], ys[16*97];
    int b = blockIdx.z, ch = blockIdx.y, dblk = blockIdx.x;
    int d0 = dblk*16;
    int tid = threadIdx.x;
    for (int i = tid; i < 16*G_; i += 256) {
        int r = i / G_, t = i % G_;
        size_t db = ((size_t)b*DM + d0 + r)*L_ + ch*G_ + t;
        size_t nb = ((size_t)b*NS + r)*L_ + ch*G_ + t;
        dls[r*97+t] = g_dl[db];
        xcs[r*97+t] = g_xc[db];
        zs [r*97+t] = g_z [db];
        bs [r*97+t] = g_Bs[nb];
        cs [r*97+t] = g_Cs[nb];
    }
    __syncthreads();
    int n = tid & 15, dloc = tid >> 4;
    int d = d0 + dloc;
    float A = -__expf(A_log[d*NS + n]);
    size_t o = (((size_t)(b*NCH + ch))*DM + d)*NS + n;
    float h = g_Hi[o];
    float Dd = Dp[d];
    for (int t = 0; t < G_; t++) {
        float dl = dls[dloc*97+t];
        float u  = xcs[dloc*97+t];
        float a = __expf(dl * A);
        h = fmaf(a, h, dl * u * bs[n*97+t]);
        float v = h * cs[n*97+t];
        v += __shfl_xor_sync(0xffffffffu, v, 1);
        v += __shfl_xor_sync(0xffffffffu, v, 2);
        v += __shfl_xor_sync(0xffffffffu, v, 4);
        v += __shfl_xor_sync(0xffffffffu, v, 8);
        if (n == 0)
            ys[dloc*97+t] = (v + u * Dd) * zs[dloc*97+t];
    }
    __syncthreads();
    /* write y pre-split as channel pairs (8 pairs x 96 tokens) */
    for (int i = tid; i < 8*G_; i += 256) {
        int r2 = i / G_, t = i % G_;
        g_y2[((size_t)b*(DM/2) + dblk*8 + r2)*L_ + ch*G_ + t] =
            bfsplit2(ys[(2*r2)*97+t], ys[(2*r2+1)*97+t]);
    }
}

/* ==== out projection: out = y @ out_w^T, pure-copy staging ==== */
__global__ void __launch_bounds__(512, 2)
gemm_out_bf(float* __restrict__ out)
{
    extern __shared__ float sm[];
    uint2* wsp = (uint2*)sm;             // 96*WSTR2
    uint2* xsp = wsp + 96*WSTR2;         // 24*XS_O
    int tid = threadIdx.x, lane = tid & 31, wid = tid >> 5;
    int tok0 = blockIdx.x * TT;
    int b = tok0 / L_, l0 = tok0 % L_;
    int wc = (wid & 1) * 48;
    int wt = (wid >> 1) * 16;

    float acc[3][2][4];
    #pragma unroll
    for (int m = 0; m < 3; m++)
        #pragma unroll
        for (int n = 0; n < 2; n++)
            #pragma unroll
            for (int q = 0; q < 4; q++) acc[m][n][q] = 0.f;

    for (int kc = 0; kc < 4; kc++) {
        __syncthreads();
        for (int i = tid; i < CDIM*24; i += 512) {
            int c = i / 24, k2 = i % 24;
            wsp[c*WSTR2 + k2] = g_wo2[(size_t)c*96 + kc*24 + k2];
        }
        for (int i = tid; i < 24*TT; i += 512) {
            int k2 = i / TT, t = i % TT;
            xsp[k2*XS_O + t] = g_y2[((size_t)b*(DM/2) + kc*24 + k2)*L_ + l0 + t];
        }
        __syncthreads();

        #pragma unroll
        for (int ks = 0; ks < 3; ks++) {
            int ksb = ks*8;
            unsigned bh[2][2], bl[2][2];
            #pragma unroll
            for (int n = 0; n < 2; n++) {
                int t = wt + n*8 + (lane>>2);
                BFRAG2(bh[n], bl[n], xsp, XS_O, ksb, t)
            }
            #pragma unroll
            for (int m = 0; m < 3; m++) {
                unsigned ah[4], al[4];
                AFRAG2(ah, al, wsp, wc + m*16 + (lane>>2), ksb)
                #pragma unroll
                for (int n = 0; n < 2; n++) {
                    mma16(acc[m][n], ah, bl[n]);
                    mma16(acc[m][n], al, bh[n]);
                    mma16(acc[m][n], ah, bh[n]);
                }
            }
        }
    }

    float* ob = out + ((size_t)b*CDIM)*L_ + l0;
    #pragma unroll
    for (int m = 0; m < 3; m++) {
        int c = wc + m*16 + (lane>>2);
        #pragma unroll
        for (int n = 0; n < 2; n++) {
            int t = wt + n*8 + 2*(lane&3);
            float2 v0, v1;
            v0.x = acc[m][n][0]; v0.y = acc[m][n][1];
            v1.x = acc[m][n][2]; v1.y = acc[m][n][3];
            *(float2*)&ob[(size_t)c*L_ + t] = v0;
            *(float2*)&ob[(size_t)(c+8)*L_ + t] = v1;
        }
    }
}

/* ============ host launcher ============ */
extern "C" void kernel_launch(void* const* d_in, const int* in_sizes, int n_in,
                              void* d_out, int out_size)
{
    const float* x         = (const float*)d_in[0];
    const float* Kin       = (const float*)d_in[1];
    const float* Qin       = (const float*)d_in[2];
    const float* in_proj_w = (const float*)d_in[3];
    const float* conv_w    = (const float*)d_in[4];
    const float* conv_b    = (const float*)d_in[5];
    const float* k_ln_g    = (const float*)d_in[6];
    const float* k_ln_b    = (const float*)d_in[7];
    const float* k_w       = (const float*)d_in[8];
    const float* k_b       = (const float*)d_in[9];
    const float* q_ln_g    = (const float*)d_in[10];
    const float* q_ln_b    = (const float*)d_in[11];
    const float* q_w       = (const float*)d_in[12];
    const float* q_b       = (const float*)d_in[13];
    const float* dtbc_w    = (const float*)d_in[14];
    const float* dt_w      = (const float*)d_in[15];
    const float* dt_b      = (const float*)d_in[16];
    const float* gate_w    = (const float*)d_in[17];
    const float* gate_b    = (const float*)d_in[18];
    const float* A_log     = (const float*)d_in[19];
    const float* Dp        = (const float*)d_in[20];
    const float* out_w     = (const float*)d_in[21];
    float* out = (float*)d_out;

    const int SMEM_G3 = (96*GT_XS + 2*(192*WSTR2 + 24*XS_G) + 128) * 4;  /* ~84 KB */
    const int SMEM_D  = (96*TTP + 38*96 + 38*TTP + 192*6 + 192) * 4;     /* ~89 KB */
    const int SMEM_GT = (2*(192*WSTR2 + 24*XS_G)) * 4;                   /* ~56 KB */
    const int SMEM_OT = (2*(96*WSTR2 + 24*XS_O)) * 4;                    /* ~47 KB */

    cudaFuncSetAttribute(gemm3_bf,    cudaFuncAttributeMaxDynamicSharedMemorySize, SMEM_G3);
    cudaFuncSetAttribute(dtbc_kernel, cudaFuncAttributeMaxDynamicSharedMemorySize, SMEM_D);
    cudaFuncSetAttribute(gate_bf,     cudaFuncAttributeMaxDynamicSharedMemorySize, SMEM_GT);
    cudaFuncSetAttribute(gemm_out_bf, cudaFuncAttributeMaxDynamicSharedMemorySize, SMEM_OT);

    /* 0. split weights once (tiny) */
    prep_w<<<(DM*192 + 3*DM*48 + CDIM*96 + 511)/512, 512>>>(in_proj_w, k_w, q_w, gate_w, out_w);
    /* 1. fused in_proj + K + Q */
    gemm3_bf<<<dim3(BL/GT_TT,3), 512, SMEM_G3>>>(x, Kin, Qin,
        k_b, k_ln_g, k_ln_b, q_b, q_ln_g, q_ln_b);
    /* 2. conv + silu (fp32 + pre-split) */
    conv_silu<<<(B_*(DM/2)*L_)/256, 256>>>(conv_w, conv_b);
    /* 2b. split Q path */
    split_qp<<<(B_*(DM/2)*L_)/256, 256>>>();
    /* 3. dtbc */
    dtbc_kernel<<<NTILE, 512, SMEM_D>>>(dtbc_w, dt_w, dt_b);
    /* 4. gate (pure-copy staging) */
    gate_bf<<<BL/GT_TT, 512, SMEM_GT>>>(gate_b);
    /* 5-7. scan */
    scan1<<<dim3(DM/16, NCH, B_), 256>>>(A_log);
    scan2<<<(B_*DM*NS)/256, 256>>>();
    scan3<<<dim3(DM/16, NCH, B_), 256>>>(A_log, Dp);
    /* 8. out projection (pure-copy staging) */
    gemm_out_bf<<<NTILE, 512, SMEM_OT>>>(out);
}

// round 17
// speedup vs baseline: 1.2503x; 1.0806x over previous
#include <cuda_runtime.h>
#include <cuda_bf16.h>

#define B_    4
#define CDIM  96
#define L_    9216
#define DM    192
#define NS    16
#define RT    6
#define BL    (B_*L_)
#define TT    128
#define NTILE (BL/TT)     /* 288 */
#define G_    96
#define NCH   (L_/G_)     /* 96 */

#define GT_TT  64
#define GT_XS  72
#define WSTR2  28         /* W smem stride in uint2 */
#define XS_G   68         /* X smem stride in uint2 (gate/gemm3) */
#define XS_O   132        /* X smem stride in uint2 (out/dtbc) */

/* ---- scratch ---- */
__device__ float g_xin[(size_t)B_*DM*L_];
__device__ float g_xc [(size_t)B_*DM*L_];
__device__ float g_dl [(size_t)B_*DM*L_];
__device__ float g_z  [(size_t)B_*DM*L_];
__device__ float g_Bs [(size_t)B_*NS*L_];
__device__ float g_Cs [(size_t)B_*NS*L_];
__device__ float g_P  [(size_t)B_*NCH*DM*NS];
__device__ float g_Hl [(size_t)B_*NCH*DM*NS];
__device__ float g_Hi [(size_t)B_*NCH*DM*NS];
/* pre-split (hi,lo) bf16 pairs, channel-pair-major activations */
__device__ uint2 g_xc2[(size_t)B_*(DM/2)*L_];
__device__ uint2 g_kp2[(size_t)B_*(DM/2)*L_];
__device__ uint2 g_qp2[(size_t)B_*(DM/2)*L_];
__device__ uint2 g_y2 [(size_t)B_*(DM/2)*L_];
/* pre-split weights */
__device__ uint2 g_wg2[(size_t)DM*192];       /* gate_w  */
__device__ uint2 g_w32[(size_t)3*DM*48];      /* in/k/q  */
__device__ uint2 g_wo2[(size_t)CDIM*96];      /* out_w   */
__device__ uint2 g_wd2[(size_t)48*192];       /* dtbc_w padded to 48 rows */

__device__ __forceinline__ float siluf(float v) { return v / (1.0f + __expf(-v)); }

__device__ __forceinline__ uint2 bfsplit2(float v0, float v1) {
    __nv_bfloat16 h0 = __float2bfloat16(v0);
    __nv_bfloat16 h1 = __float2bfloat16(v1);
    __nv_bfloat16 l0 = __float2bfloat16(v0 - __bfloat162float(h0));
    __nv_bfloat16 l1 = __float2bfloat16(v1 - __bfloat162float(h1));
    uint2 r;
    r.x = ((unsigned)__bfloat16_as_ushort(h1) << 16) | __bfloat16_as_ushort(h0);
    r.y = ((unsigned)__bfloat16_as_ushort(l1) << 16) | __bfloat16_as_ushort(l0);
    return r;
}

__device__ __forceinline__ void mma16(float* d, const unsigned* a, const unsigned* b) {
    asm volatile("mma.sync.aligned.m16n8k16.row.col.f32.bf16.bf16.f32 "
        "{%0,%1,%2,%3}, {%4,%5,%6,%7}, {%8,%9}, {%0,%1,%2,%3};"
        : "+f"(d[0]), "+f"(d[1]), "+f"(d[2]), "+f"(d[3])
        : "r"(a[0]), "r"(a[1]), "r"(a[2]), "r"(a[3]), "r"(b[0]), "r"(b[1]));
}

#define AFRAG2(AH, AL_, Wp, c, ksb) {                                     \
    uint2 q0_ = (Wp)[(c)*WSTR2 + (ksb) + (lane&3)];                       \
    uint2 q1_ = (Wp)[((c)+8)*WSTR2 + (ksb) + (lane&3)];                   \
    uint2 q2_ = (Wp)[(c)*WSTR2 + (ksb) + (lane&3) + 4];                   \
    uint2 q3_ = (Wp)[((c)+8)*WSTR2 + (ksb) + (lane&3) + 4];               \
    AH[0]=q0_.x; AH[1]=q1_.x; AH[2]=q2_.x; AH[3]=q3_.x;                   \
    AL_[0]=q0_.y; AL_[1]=q1_.y; AL_[2]=q2_.y; AL_[3]=q3_.y; }

#define BFRAG2(BH, BL_, Xp, XSTR, ksb, t) {                               \
    uint2 q0_ = (Xp)[((ksb) + (lane&3))*(XSTR) + (t)];                    \
    uint2 q1_ = (Xp)[((ksb) + (lane&3) + 4)*(XSTR) + (t)];                \
    BH[0]=q0_.x; BH[1]=q1_.x; BL_[0]=q0_.y; BL_[1]=q1_.y; }

/* ============ weight pre-split (once, tiny) ============ */
__global__ void __launch_bounds__(512)
prep_w(const float* __restrict__ in_w, const float* __restrict__ k_w,
       const float* __restrict__ q_w, const float* __restrict__ gate_w,
       const float* __restrict__ out_w, const float* __restrict__ dtbc_w)
{
    int i = blockIdx.x*512 + threadIdx.x;
    if (i < DM*192) {
        int c = i / 192, k2 = i % 192;
        g_wg2[i] = bfsplit2(gate_w[(size_t)c*384 + 2*k2], gate_w[(size_t)c*384 + 2*k2 + 1]);
    } else if (i < DM*192 + 3*DM*48) {
        int j = i - DM*192;
        int s = j / (DM*48), r = j % (DM*48);
        int c = r / 48, k2 = r % 48;
        const float* W = (s==0) ? in_w : (s==1 ? k_w : q_w);
        g_w32[j] = bfsplit2(W[(size_t)c*96 + 2*k2], W[(size_t)c*96 + 2*k2 + 1]);
    } else if (i < DM*192 + 3*DM*48 + CDIM*96) {
        int j = i - (DM*192 + 3*DM*48);
        int c = j / 96, k2 = j % 96;
        g_wo2[j] = bfsplit2(out_w[(size_t)c*192 + 2*k2], out_w[(size_t)c*192 + 2*k2 + 1]);
    } else if (i < DM*192 + 3*DM*48 + CDIM*96 + 48*192) {
        int j = i - (DM*192 + 3*DM*48 + CDIM*96);
        int c = j / 192, k2 = j % 192;
        uint2 z; z.x = 0u; z.y = 0u;
        g_wd2[j] = (c < 38) ? bfsplit2(dtbc_w[(size_t)c*384 + 2*k2],
                                       dtbc_w[(size_t)c*384 + 2*k2 + 1]) : z;
    }
}

/* ==== fused 3x GEMM (in_proj / K / Q), LN fused; K/Q emit pre-split ==== */
__global__ void __launch_bounds__(512, 2)
gemm3_bf(const float* __restrict__ x, const float* __restrict__ Kin,
         const float* __restrict__ Qin,
         const float* __restrict__ k_b, const float* __restrict__ k_ln_g,
         const float* __restrict__ k_ln_b, const float* __restrict__ q_b,
         const float* __restrict__ q_ln_g, const float* __restrict__ q_ln_b)
{
    extern __shared__ float sm[];
    float* xs = sm;                              // 96*GT_XS raw
    uint2* wsp = (uint2*)(sm + 96*GT_XS);        // 192*WSTR2
    uint2* xsp = wsp + 192*WSTR2;                // 24*XS_G
    float* mean_s = (float*)(xsp + 24*XS_G);
    float* rstd_s = mean_s + 64;

    int sel = blockIdx.y;
    const float* src  = (sel==0) ? x : (sel==1 ? Kin : Qin);
    const float* bias = (sel==1) ? k_b : q_b;
    const float* lng  = (sel==1) ? k_ln_g : q_ln_g;
    const float* lnb  = (sel==1) ? k_ln_b : q_ln_b;
    const uint2* wsrc = g_w32 + (size_t)sel*DM*48;

    int tid = threadIdx.x, lane = tid & 31, wid = tid >> 5;
    int tok0 = blockIdx.x * GT_TT;
    int b = tok0 / L_, l0 = tok0 % L_;
    const float* srcb = src + ((size_t)b*CDIM)*L_ + l0;

    for (int i = tid; i < CDIM*GT_TT; i += 512) {
        int t = i % GT_TT, k = i / GT_TT;
        xs[k*GT_XS + t] = srcb[(size_t)k*L_ + t];
    }
    __syncthreads();

    if (sel != 0) {
        if (tid < GT_TT) {
            float s = 0.f, ss = 0.f;
            for (int c = 0; c < CDIM; c++) { float v = xs[c*GT_XS + tid]; s += v; ss += v*v; }
            float m = s * (1.0f/CDIM);
            float var = ss * (1.0f/CDIM) - m*m;
            mean_s[tid] = m; rstd_s[tid] = rsqrtf(var + 1e-5f);
        }
        __syncthreads();
        for (int i = tid; i < CDIM*GT_TT; i += 512) {
            int t = i % GT_TT, c = i / GT_TT;
            xs[c*GT_XS + t] = (xs[c*GT_XS + t] - mean_s[t]) * rstd_s[t] * lng[c] + lnb[c];
        }
    }

    int wc = (wid & 3) * 48;
    int wt = (wid >> 2) * 16;

    float acc[3][2][4];
    #pragma unroll
    for (int m = 0; m < 3; m++)
        #pragma unroll
        for (int n = 0; n < 2; n++)
            #pragma unroll
            for (int q = 0; q < 4; q++) acc[m][n][q] = 0.f;

    for (int kc = 0; kc < 2; kc++) {
        __syncthreads();
        for (int i = tid; i < DM*24; i += 512) {
            int c = i / 24, k2 = i % 24;
            wsp[c*WSTR2 + k2] = wsrc[(size_t)c*48 + kc*24 + k2];
        }
        for (int i = tid; i < 24*GT_TT; i += 512) {
            int k2 = i / GT_TT, t = i % GT_TT;
            float v0 = xs[(kc*48 + 2*k2)*GT_XS + t];
            float v1 = xs[(kc*48 + 2*k2 + 1)*GT_XS + t];
            xsp[k2*XS_G + t] = bfsplit2(v0, v1);
        }
        __syncthreads();

        #pragma unroll
        for (int ks = 0; ks < 3; ks++) {
            int ksb = ks*8;
            unsigned bh[2][2], bl[2][2];
            #pragma unroll
            for (int n = 0; n < 2; n++) {
                int t = wt + n*8 + (lane>>2);
                BFRAG2(bh[n], bl[n], xsp, XS_G, ksb, t)
            }
            #pragma unroll
            for (int m = 0; m < 3; m++) {
                unsigned ah[4], al[4];
                AFRAG2(ah, al, wsp, wc + m*16 + (lane>>2), ksb)
                #pragma unroll
                for (int n = 0; n < 2; n++) {
                    mma16(acc[m][n], ah, bl[n]);
                    mma16(acc[m][n], al, bh[n]);
                    mma16(acc[m][n], ah, bh[n]);
                }
            }
        }
    }

    if (sel == 0) {
        float* dstb = g_xin + ((size_t)b*DM)*L_ + l0;
        #pragma unroll
        for (int m = 0; m < 3; m++) {
            int c = wc + m*16 + (lane>>2);
            #pragma unroll
            for (int n = 0; n < 2; n++) {
                int t = wt + n*8 + 2*(lane&3);
                float2 v0, v1;
                v0.x = acc[m][n][0]; v0.y = acc[m][n][1];
                v1.x = acc[m][n][2]; v1.y = acc[m][n][3];
                *(float2*)&dstb[(size_t)c*L_ + t] = v0;
                *(float2*)&dstb[(size_t)(c+8)*L_ + t] = v1;
            }
        }
    } else {
        /* K/Q: apply bias+silu, round-trip through smem, emit pre-split pairs */
        __syncthreads();
        float* res = (float*)wsp;   /* 192*68 floats, overlays wsp+xsp */
        #pragma unroll
        for (int m = 0; m < 3; m++) {
            int c = wc + m*16 + (lane>>2);
            float bv0 = bias[c], bv1 = bias[c+8];
            #pragma unroll
            for (int n = 0; n < 2; n++) {
                int t = wt + n*8 + 2*(lane&3);
                float2 v0, v1;
                v0.x = siluf(acc[m][n][0] + bv0); v0.y = siluf(acc[m][n][1] + bv0);
                v1.x = siluf(acc[m][n][2] + bv1); v1.y = siluf(acc[m][n][3] + bv1);
                *(float2*)&res[c*68 + t] = v0;
                *(float2*)&res[(c+8)*68 + t] = v1;
            }
        }
        __syncthreads();
        uint2* dst2 = (sel == 1) ? g_kp2 : g_qp2;
        for (int i = tid; i < (DM/2)*GT_TT; i += 512) {
            int d2 = i / GT_TT, t = i % GT_TT;
            dst2[((size_t)b*(DM/2) + d2)*L_ + l0 + t] =
                bfsplit2(res[(2*d2)*68 + t], res[(2*d2+1)*68 + t]);
        }
    }
}

/* ============ conv (2 channels/thread) + silu, fp32 + pre-split ============ */
__global__ void __launch_bounds__(256)
conv_silu(const float* __restrict__ cw, const float* __restrict__ cb)
{
    int gid = blockIdx.x * blockDim.x + threadIdx.x;
    if (gid >= B_*(DM/2)*L_) return;
    int l   = gid % L_;
    int bd2 = gid / L_;
    int d2  = bd2 % (DM/2);
    int b   = bd2 / (DM/2);
    int d   = 2*d2;
    const float* p0 = g_xin + (((size_t)b*DM + d)*L_) + l;
    const float* p1 = p0 + L_;
    float a0 = cb[d]   + cw[d*4+3]     * p0[0];
    float a1 = cb[d+1] + cw[(d+1)*4+3] * p1[0];
    if (l >= 1) { a0 = fmaf(cw[d*4+2], p0[-1], a0); a1 = fmaf(cw[(d+1)*4+2], p1[-1], a1); }
    if (l >= 2) { a0 = fmaf(cw[d*4+1], p0[-2], a0); a1 = fmaf(cw[(d+1)*4+1], p1[-2], a1); }
    if (l >= 3) { a0 = fmaf(cw[d*4+0], p0[-3], a0); a1 = fmaf(cw[(d+1)*4+0], p1[-3], a1); }
    float s0 = siluf(a0), s1 = siluf(a1);
    g_xc[((size_t)b*DM + d)*L_ + l]     = s0;
    g_xc[((size_t)b*DM + d + 1)*L_ + l] = s1;
    g_xc2[((size_t)b*(DM/2) + d2)*L_ + l] = bfsplit2(s0, s1);
}

/* ==== dtbc on tensor cores: x_dbl(48) = cat(xc,kp) @ wd^T; then delta/B/C ====
   256 thr = 8 warps x 16 tokens, 128-token tile, K=384 in 8 chunks of 48. */
__global__ void __launch_bounds__(256, 4)
dtbc_bf(const float* __restrict__ dt_w, const float* __restrict__ dt_b)
{
    extern __shared__ float sm[];
    uint2* wsp = (uint2*)sm;                 // 48*WSTR2
    uint2* xsp = wsp + 48*WSTR2;             // 24*XS_O
    float* dtw = (float*)(xsp + 24*XS_O);    // 192*6
    float* dtb = dtw + DM*RT;                // 192
    float* dbl = (float*)xsp;                // overlay after MMA: 38*XS_O floats

    int tid = threadIdx.x, lane = tid & 31, wid = tid >> 5;
    int tok0 = blockIdx.x * TT;
    int b = tok0 / L_, l0 = tok0 % L_;
    int wt = wid * 16;

    for (int i = tid; i < DM*RT; i += 256) dtw[i] = dt_w[i];
    for (int i = tid; i < DM;    i += 256) dtb[i] = dt_b[i];

    float acc[3][2][4];
    #pragma unroll
    for (int m = 0; m < 3; m++)
        #pragma unroll
        for (int n = 0; n < 2; n++)
            #pragma unroll
            for (int q = 0; q < 4; q++) acc[m][n][q] = 0.f;

    for (int kc = 0; kc < 8; kc++) {
        const uint2* src2 = (kc < 4) ? g_xc2 : g_kp2;
        int ch2 = (kc & 3) * 24;
        __syncthreads();
        for (int i = tid; i < 48*24; i += 256) {
            int c = i / 24, k2 = i % 24;
            wsp[c*WSTR2 + k2] = g_wd2[(size_t)c*192 + kc*24 + k2];
        }
        for (int i = tid; i < 24*TT; i += 256) {
            int k2 = i / TT, t = i % TT;
            xsp[k2*XS_O + t] = src2[((size_t)b*(DM/2) + ch2 + k2)*L_ + l0 + t];
        }
        __syncthreads();

        #pragma unroll
        for (int ks = 0; ks < 3; ks++) {
            int ksb = ks*8;
            unsigned bh[2][2], bl[2][2];
            #pragma unroll
            for (int n = 0; n < 2; n++) {
                int t = wt + n*8 + (lane>>2);
                BFRAG2(bh[n], bl[n], xsp, XS_O, ksb, t)
            }
            #pragma unroll
            for (int m = 0; m < 3; m++) {
                unsigned ah[4], al[4];
                AFRAG2(ah, al, wsp, m*16 + (lane>>2), ksb)
                #pragma unroll
                for (int n = 0; n < 2; n++) {
                    mma16(acc[m][n], ah, bl[n]);
                    mma16(acc[m][n], al, bh[n]);
                    mma16(acc[m][n], ah, bh[n]);
                }
            }
        }
    }

    __syncthreads();
    /* x_dbl rows 0..37 into dbl smem */
    #pragma unroll
    for (int m = 0; m < 3; m++) {
        int c = m*16 + (lane>>2);
        #pragma unroll
        for (int n = 0; n < 2; n++) {
            int t = wt + n*8 + 2*(lane&3);
            if (c < 38) {
                float2 v; v.x = acc[m][n][0]; v.y = acc[m][n][1];
                *(float2*)&dbl[c*XS_O + t] = v;
            }
            if (c + 8 < 38) {
                float2 v; v.x = acc[m][n][2]; v.y = acc[m][n][3];
                *(float2*)&dbl[(c+8)*XS_O + t] = v;
            }
        }
    }
    __syncthreads();

    /* delta = softplus(dt @ dt_w^T + 2*dt_b) */
    for (int i = tid; i < DM*TT; i += 256) {
        int t = i % TT, d = i / TT;
        float s = 2.0f * dtb[d];
        #pragma unroll
        for (int r = 0; r < RT; r++) s = fmaf(dbl[r*XS_O + t], dtw[d*RT + r], s);
        float dl = (s > 20.f) ? s : log1pf(__expf(s));
        g_dl[((size_t)b*DM + d)*L_ + l0 + t] = dl;
    }
    for (int i = tid; i < 2*NS*TT; i += 256) {
        int t = i % TT, q = i / TT;
        float v = dbl[(RT + q)*XS_O + t];
        if (q < NS) g_Bs[((size_t)b*NS + q)*L_ + l0 + t] = v;
        else        g_Cs[((size_t)b*NS + (q-NS))*L_ + l0 + t] = v;
    }
}

/* ==== gate: z = silu(cat(xc,qp) @ gate_w^T + b), pure-copy staging ==== */
__global__ void __launch_bounds__(512, 2)
gate_bf(const float* __restrict__ gate_b)
{
    extern __shared__ float sm[];
    uint2* wsp = (uint2*)sm;             // 192*WSTR2
    uint2* xsp = wsp + 192*WSTR2;        // 24*XS_G
    int tid = threadIdx.x, lane = tid & 31, wid = tid >> 5;
    int tok0 = blockIdx.x * GT_TT;
    int b = tok0 / L_, l0 = tok0 % L_;
    int wc = (wid & 3) * 48;
    int wt = (wid >> 2) * 16;

    float acc[3][2][4];
    #pragma unroll
    for (int m = 0; m < 3; m++)
        #pragma unroll
        for (int n = 0; n < 2; n++)
            #pragma unroll
            for (int q = 0; q < 4; q++) acc[m][n][q] = 0.f;

    for (int kc = 0; kc < 8; kc++) {
        const uint2* src2 = (kc < 4) ? g_xc2 : g_qp2;
        int ch2 = (kc & 3) * 24;
        __syncthreads();
        for (int i = tid; i < DM*24; i += 512) {
            int c = i / 24, k2 = i % 24;
            wsp[c*WSTR2 + k2] = g_wg2[(size_t)c*192 + kc*24 + k2];
        }
        for (int i = tid; i < 24*GT_TT; i += 512) {
            int k2 = i / GT_TT, t = i % GT_TT;
            xsp[k2*XS_G + t] = src2[((size_t)b*(DM/2) + ch2 + k2)*L_ + l0 + t];
        }
        __syncthreads();

        #pragma unroll
        for (int ks = 0; ks < 3; ks++) {
            int ksb = ks*8;
            unsigned bh[2][2], bl[2][2];
            #pragma unroll
            for (int n = 0; n < 2; n++) {
                int t = wt + n*8 + (lane>>2);
                BFRAG2(bh[n], bl[n], xsp, XS_G, ksb, t)
            }
            #pragma unroll
            for (int m = 0; m < 3; m++) {
                unsigned ah[4], al[4];
                AFRAG2(ah, al, wsp, wc + m*16 + (lane>>2), ksb)
                #pragma unroll
                for (int n = 0; n < 2; n++) {
                    mma16(acc[m][n], ah, bl[n]);
                    mma16(acc[m][n], al, bh[n]);
                    mma16(acc[m][n], ah, bh[n]);
                }
            }
        }
    }

    float* dstb = g_z + ((size_t)b*DM)*L_ + l0;
    #pragma unroll
    for (int m = 0; m < 3; m++) {
        int c = wc + m*16 + (lane>>2);
        float bv0 = gate_b[c], bv1 = gate_b[c+8];
        #pragma unroll
        for (int n = 0; n < 2; n++) {
            int t = wt + n*8 + 2*(lane&3);
            float2 v0, v1;
            v0.x = siluf(acc[m][n][0] + bv0); v0.y = siluf(acc[m][n][1] + bv0);
            v1.x = siluf(acc[m][n][2] + bv1); v1.y = siluf(acc[m][n][3] + bv1);
            *(float2*)&dstb[(size_t)c*L_ + t] = v0;
            *(float2*)&dstb[(size_t)(c+8)*L_ + t] = v1;
        }
    }
}

/* ============ chunked selective scan ============ */
__global__ void __launch_bounds__(256)
scan1(const float* __restrict__ A_log)
{
    __shared__ float dls[16*97], xcs[16*97], bs[16*97];
    int b = blockIdx.z, ch = blockIdx.y, dblk = blockIdx.x;
    int d0 = dblk*16;
    int tid = threadIdx.x;
    for (int i = tid; i < 16*G_; i += 256) {
        int r = i / G_, t = i % G_;
        dls[r*97+t] = g_dl[((size_t)b*DM + d0 + r)*L_ + ch*G_ + t];
        xcs[r*97+t] = g_xc[((size_t)b*DM + d0 + r)*L_ + ch*G_ + t];
        bs [r*97+t] = g_Bs[((size_t)b*NS + r)*L_ + ch*G_ + t];
    }
    __syncthreads();
    int n = tid & 15, dloc = tid >> 4;
    int d = d0 + dloc;
    float A = -__expf(A_log[d*NS + n]);
    float h = 0.f, S = 0.f;
    #pragma unroll 4
    for (int t = 0; t < G_; t++) {
        float dl = dls[dloc*97+t];
        float a = __expf(dl * A);
        S += dl;
        h = fmaf(a, h, dl * xcs[dloc*97+t] * bs[n*97+t]);
    }
    size_t o = (((size_t)(b*NCH + ch))*DM + d)*NS + n;
    g_P[o] = __expf(A * S); g_Hl[o] = h;
}

__global__ void __launch_bounds__(256)
scan2()
{
    int idx = blockIdx.x * blockDim.x + threadIdx.x;
    if (idx >= B_*DM*NS) return;
    int b = idx / (DM*NS);
    int dn = idx % (DM*NS);
    float h = 0.f;
    for (int ch = 0; ch < NCH; ch++) {
        size_t o = ((size_t)(b*NCH + ch))*(DM*NS) + dn;
        g_Hi[o] = h;
        h = fmaf(g_P[o], h, g_Hl[o]);
    }
}

__global__ void __launch_bounds__(256)
scan3(const float* __restrict__ A_log, const float* __restrict__ Dp)
{
    __shared__ float dls[16*97], xcs[16*97], bs[16*97], cs[16*97], zs[16*97], ys[16*97];
    int b = blockIdx.z, ch = blockIdx.y, dblk = blockIdx.x;
    int d0 = dblk*16;
    int tid = threadIdx.x;
    for (int i = tid; i < 16*G_; i += 256) {
        int r = i / G_, t = i % G_;
        size_t db = ((size_t)b*DM + d0 + r)*L_ + ch*G_ + t;
        size_t nb = ((size_t)b*NS + r)*L_ + ch*G_ + t;
        dls[r*97+t] = g_dl[db];
        xcs[r*97+t] = g_xc[db];
        zs [r*97+t] = g_z [db];
        bs [r*97+t] = g_Bs[nb];
        cs [r*97+t] = g_Cs[nb];
    }
    __syncthreads();
    int n = tid & 15, dloc = tid >> 4;
    int d = d0 + dloc;
    float A = -__expf(A_log[d*NS + n]);
    size_t o = (((size_t)(b*NCH + ch))*DM + d)*NS + n;
    float h = g_Hi[o];
    float Dd = Dp[d];
    for (int t = 0; t < G_; t++) {
        float dl = dls[dloc*97+t];
        float u  = xcs[dloc*97+t];
        float a = __expf(dl * A);
        h = fmaf(a, h, dl * u * bs[n*97+t]);
        float v = h * cs[n*97+t];
        v += __shfl_xor_sync(0xffffffffu, v, 1);
        v += __shfl_xor_sync(0xffffffffu, v, 2);
        v += __shfl_xor_sync(0xffffffffu, v, 4);
        v += __shfl_xor_sync(0xffffffffu, v, 8);
        if (n == 0)
            ys[dloc*97+t] = (v + u * Dd) * zs[dloc*97+t];
    }
    __syncthreads();
    for (int i = tid; i < 8*G_; i += 256) {
        int r2 = i / G_, t = i % G_;
        g_y2[((size_t)b*(DM/2) + dblk*8 + r2)*L_ + ch*G_ + t] =
            bfsplit2(ys[(2*r2)*97+t], ys[(2*r2+1)*97+t]);
    }
}

/* ==== out projection: out = y @ out_w^T, pure-copy staging ==== */
__global__ void __launch_bounds__(512, 2)
gemm_out_bf(float* __restrict__ out)
{
    extern __shared__ float sm[];
    uint2* wsp = (uint2*)sm;             // 96*WSTR2
    uint2* xsp = wsp + 96*WSTR2;         // 24*XS_O
    int tid = threadIdx.x, lane = tid & 31, wid = tid >> 5;
    int tok0 = blockIdx.x * TT;
    int b = tok0 / L_, l0 = tok0 % L_;
    int wc = (wid & 1) * 48;
    int wt = (wid >> 1) * 16;

    float acc[3][2][4];
    #pragma unroll
    for (int m = 0; m < 3; m++)
        #pragma unroll
        for (int n = 0; n < 2; n++)
            #pragma unroll
            for (int q = 0; q < 4; q++) acc[m][n][q] = 0.f;

    for (int kc = 0; kc < 4; kc++) {
        __syncthreads();
        for (int i = tid; i < CDIM*24; i += 512) {
            int c = i / 24, k2 = i % 24;
            wsp[c*WSTR2 + k2] = g_wo2[(size_t)c*96 + kc*24 + k2];
        }
        for (int i = tid; i < 24*TT; i += 512) {
            int k2 = i / TT, t = i % TT;
            xsp[k2*XS_O + t] = g_y2[((size_t)b*(DM/2) + kc*24 + k2)*L_ + l0 + t];
        }
        __syncthreads();

        #pragma unroll
        for (int ks = 0; ks < 3; ks++) {
            int ksb = ks*8;
            unsigned bh[2][2], bl[2][2];
            #pragma unroll
            for (int n = 0; n < 2; n++) {
                int t = wt + n*8 + (lane>>2);
                BFRAG2(bh[n], bl[n], xsp, XS_O, ksb, t)
            }
            #pragma unroll
            for (int m = 0; m < 3; m++) {
                unsigned ah[4], al[4];
                AFRAG2(ah, al, wsp, wc + m*16 + (lane>>2), ksb)
                #pragma unroll
                for (int n = 0; n < 2; n++) {
                    mma16(acc[m][n], ah, bl[n]);
                    mma16(acc[m][n], al, bh[n]);
                    mma16(acc[m][n], ah, bh[n]);
                }
            }
        }
    }

    float* ob = out + ((size_t)b*CDIM)*L_ + l0;
    #pragma unroll
    for (int m = 0; m < 3; m++) {
        int c = wc + m*16 + (lane>>2);
        #pragma unroll
        for (int n = 0; n < 2; n++) {
            int t = wt + n*8 + 2*(lane&3);
            float2 v0, v1;
            v0.x = acc[m][n][0]; v0.y = acc[m][n][1];
            v1.x = acc[m][n][2]; v1.y = acc[m][n][3];
            *(float2*)&ob[(size_t)c*L_ + t] = v0;
            *(float2*)&ob[(size_t)(c+8)*L_ + t] = v1;
        }
    }
}

/* ============ host launcher ============ */
extern "C" void kernel_launch(void* const* d_in, const int* in_sizes, int n_in,
                              void* d_out, int out_size)
{
    const float* x         = (const float*)d_in[0];
    const float* Kin       = (const float*)d_in[1];
    const float* Qin       = (const float*)d_in[2];
    const float* in_proj_w = (const float*)d_in[3];
    const float* conv_w    = (const float*)d_in[4];
    const float* conv_b    = (const float*)d_in[5];
    const float* k_ln_g    = (const float*)d_in[6];
    const float* k_ln_b    = (const float*)d_in[7];
    const float* k_w       = (const float*)d_in[8];
    const float* k_b       = (const float*)d_in[9];
    const float* q_ln_g    = (const float*)d_in[10];
    const float* q_ln_b    = (const float*)d_in[11];
    const float* q_w       = (const float*)d_in[12];
    const float* q_b       = (const float*)d_in[13];
    const float* dtbc_w    = (const float*)d_in[14];
    const float* dt_w      = (const float*)d_in[15];
    const float* dt_b      = (const float*)d_in[16];
    const float* gate_w    = (const float*)d_in[17];
    const float* gate_b    = (const float*)d_in[18];
    const float* A_log     = (const float*)d_in[19];
    const float* Dp        = (const float*)d_in[20];
    const float* out_w     = (const float*)d_in[21];
    float* out = (float*)d_out;

    const int SMEM_G3 = (96*GT_XS + 2*(192*WSTR2 + 24*XS_G) + 128) * 4;  /* ~84 KB */
    const int SMEM_DT = (2*(48*WSTR2 + 24*XS_O) + DM*RT + DM) * 4;       /* ~42 KB */
    const int SMEM_GT = (2*(192*WSTR2 + 24*XS_G)) * 4;                   /* ~56 KB */
    const int SMEM_OT = (2*(96*WSTR2 + 24*XS_O)) * 4;                    /* ~47 KB */

    cudaFuncSetAttribute(gemm3_bf,    cudaFuncAttributeMaxDynamicSharedMemorySize, SMEM_G3);
    cudaFuncSetAttribute(dtbc_bf,     cudaFuncAttributeMaxDynamicSharedMemorySize, SMEM_DT);
    cudaFuncSetAttribute(gate_bf,     cudaFuncAttributeMaxDynamicSharedMemorySize, SMEM_GT);
    cudaFuncSetAttribute(gemm_out_bf, cudaFuncAttributeMaxDynamicSharedMemorySize, SMEM_OT);

    /* 0. split weights once */
    prep_w<<<(DM*192 + 3*DM*48 + CDIM*96 + 48*192 + 511)/512, 512>>>(
        in_proj_w, k_w, q_w, gate_w, out_w, dtbc_w);
    /* 1. fused in_proj + K + Q (K/Q emit pre-split directly) */
    gemm3_bf<<<dim3(BL/GT_TT,3), 512, SMEM_G3>>>(x, Kin, Qin,
        k_b, k_ln_g, k_ln_b, q_b, q_ln_g, q_ln_b);
    /* 2. conv + silu (fp32 + pre-split) */
    conv_silu<<<(B_*(DM/2)*L_)/256, 256>>>(conv_w, conv_b);
    /* 3. dtbc on tensor cores */
    dtbc_bf<<<NTILE, 256, SMEM_DT>>>(dt_w, dt_b);
    /* 4. gate */
    gate_bf<<<BL/GT_TT, 512, SMEM_GT>>>(gate_b);
    /* 5-7. scan */
    scan1<<<dim3(DM/16, NCH, B_), 256>>>(A_log);
    scan2<<<(B_*DM*NS)/256, 256>>>();
    scan3<<<dim3(DM/16, NCH, B_), 256>>>(A_log, Dp);
    /* 8. out projection */
    gemm_out_bf<<<NTILE, 512, SMEM_OT>>>(out);
}